// round 2
// baseline (speedup 1.0000x reference)
#include <cuda_runtime.h>
#include <math.h>

#define BB 8
#define CC 64
#define NN 1000
#define TT 24
#define RR 10
#define NT 24000     // NN*TT
#define CT 1536      // CC*TT
#define NCO 64000    // NN*CC

// ------------------------- scratch (device globals, no allocs) -------------
__device__ float g_x1[BB*CC*NT];          // x1 [b,c,n,t]
__device__ float g_s1a[BB*CC*RR];
__device__ float g_s2a[BB*RR*CC];
__device__ float g_att0[BB*CC*CC];
__device__ float g_s1g[BB*NN*RR];
__device__ float g_s2g[BB*RR*NN];
__device__ float g_Ag[BB*NN*NN];          // gated adjacency [b,n,m]
__device__ float g_y[BB*NN*CT];           // (x1 . gcn_W)  [b,m,(o*T+t)]
__device__ float g_gb[BB*NN*CT];          // g             [b,n,(o*T+t)]
__device__ float g_s1t[BB*TT*RR];
__device__ float g_s2t[BB*RR*TT];
__device__ float g_attT[BB*TT*TT];
// transposed weights
__device__ float g_a0W1T[RR*NT];
__device__ float g_gW1T[RR*CT];
__device__ float g_tW1T[RR*NCO];
__device__ float g_w1T[2*CC*CC];          // conv1 [tap][c][o]
__device__ float g_w2T[2*CC*CC];          // conv2 [tap][c][o]
__device__ float g_rT[CC*CC];             // res_w [c][o]

// ------------------------- K0: weight prep (transposes) --------------------
__global__ void k_prep(const float* __restrict__ a0W1, const float* __restrict__ gW1,
                       const float* __restrict__ tW1, const float* __restrict__ c1w,
                       const float* __restrict__ c2w, const float* __restrict__ rw) {
    int e = blockIdx.x * 256 + threadIdx.x;
    if (e < NT*RR)  { int k = e/RR, r = e - k*RR; g_a0W1T[r*NT + k] = a0W1[e]; return; }
    e -= NT*RR;
    if (e < CT*RR)  { int k = e/RR, r = e - k*RR; g_gW1T[r*CT + k] = gW1[e]; return; }
    e -= CT*RR;
    if (e < NCO*RR) { int k = e/RR, r = e - k*RR; g_tW1T[r*NCO + k] = tW1[e]; return; }
    e -= NCO*RR;
    if (e < CC*CC) {
        int o = e >> 6, c = e & 63;
        g_w1T[c*CC + o]         = c1w[e*2 + 0];
        g_w1T[CC*CC + c*CC + o] = c1w[e*2 + 1];
        g_w2T[c*CC + o]         = c2w[e*2 + 0];
        g_w2T[CC*CC + c*CC + o] = c2w[e*2 + 1];
        g_rT[c*CC + o]          = rw[e];
    }
}

// ------------------------- K1: channel-attn projections --------------------
// s1[b,c,r] = sum_k xf[b,c,k]*W1[k,r];  s2[b,r,c] = sum_k W2[r,k]*xf[b,c,k]
__global__ void k_attA_proj(const float* __restrict__ x, const float* __restrict__ W2) {
    int bc = blockIdx.x;                       // b*64 + c
    const float* xf = x + (size_t)bc * NT;
    float a1[RR], a2[RR];
#pragma unroll
    for (int r = 0; r < RR; r++) { a1[r] = 0.f; a2[r] = 0.f; }
    for (int k = threadIdx.x; k < NT; k += 256) {
        float xv = xf[k];
#pragma unroll
        for (int r = 0; r < RR; r++) {
            a1[r] += xv * g_a0W1T[r*NT + k];
            a2[r] += xv * W2[r*NT + k];
        }
    }
    __shared__ float red[8][2*RR];
    int lane = threadIdx.x & 31, warp = threadIdx.x >> 5;
#pragma unroll
    for (int r = 0; r < RR; r++) {
#pragma unroll
        for (int off = 16; off > 0; off >>= 1) {
            a1[r] += __shfl_down_sync(0xffffffffu, a1[r], off);
            a2[r] += __shfl_down_sync(0xffffffffu, a2[r], off);
        }
    }
    if (lane == 0) {
#pragma unroll
        for (int r = 0; r < RR; r++) { red[warp][r] = a1[r]; red[warp][RR+r] = a2[r]; }
    }
    __syncthreads();
    if (threadIdx.x < 2*RR) {
        float s = 0.f;
#pragma unroll
        for (int w = 0; w < 8; w++) s += red[w][threadIdx.x];
        int b = bc >> 6, c = bc & 63;
        if (threadIdx.x < RR) g_s1a[(b*CC + c)*RR + threadIdx.x] = s;
        else                  g_s2a[(b*RR + (threadIdx.x - RR))*CC + c] = s;
    }
}

// ------------------------- K2: channel-attn softmax (64x64) ----------------
__global__ void k_attA_soft() {
    int b = blockIdx.x >> 6, i = blockIdx.x & 63;
    int j = threadIdx.x;                       // 64 threads
    float s = 0.f;
#pragma unroll
    for (int r = 0; r < RR; r++) s += g_s1a[(b*CC + i)*RR + r] * g_s2a[(b*RR + r)*CC + j];
    s *= rsqrtf((float)NT);
    __shared__ float sm[CC];
    sm[j] = s; __syncthreads();
    float mx = -1e30f;
    for (int jj = 0; jj < CC; jj++) mx = fmaxf(mx, sm[jj]);
    float e = expf(s - mx);
    __syncthreads();
    sm[j] = e; __syncthreads();
    float sum = 0.f;
    for (int jj = 0; jj < CC; jj++) sum += sm[jj];
    g_att0[(b*CC + i)*CC + j] = e / sum;
}

// ------------------------- K3: x1 = att0 @ xf -------------------------------
__global__ void k_chan_apply(const float* __restrict__ x) {
    int b = blockIdx.y;
    int k0 = blockIdx.x * 64;
    __shared__ float attsT[CC][68];            // [j][c], padded
    __shared__ float xfs[CC][64];              // [j][kk]
    int tid = threadIdx.x;                     // 256
    for (int e = tid; e < CC*CC; e += 256) {
        int c = e >> 6, j = e & 63;
        attsT[j][c] = g_att0[b*CC*CC + e];
    }
    for (int e = tid; e < CC*64; e += 256) {
        int j = e >> 6, kk = e & 63;
        xfs[j][kk] = x[(size_t)(b*CC + j)*NT + k0 + kk];
    }
    __syncthreads();
    int kk = tid & 63, cg = tid >> 6;          // cg: 0..3 -> 16 c's each
    float4 acc[4];
#pragma unroll
    for (int q = 0; q < 4; q++) acc[q] = make_float4(0.f, 0.f, 0.f, 0.f);
    for (int j = 0; j < CC; j++) {
        float xv = xfs[j][kk];
        const float4* ap = (const float4*)&attsT[j][cg*16];
#pragma unroll
        for (int q = 0; q < 4; q++) {
            float4 a = ap[q];
            acc[q].x += a.x * xv; acc[q].y += a.y * xv;
            acc[q].z += a.z * xv; acc[q].w += a.w * xv;
        }
    }
#pragma unroll
    for (int q = 0; q < 4; q++) {
        int c = cg*16 + q*4;
        g_x1[(size_t)(b*CC + c + 0)*NT + k0 + kk] = acc[q].x;
        g_x1[(size_t)(b*CC + c + 1)*NT + k0 + kk] = acc[q].y;
        g_x1[(size_t)(b*CC + c + 2)*NT + k0 + kk] = acc[q].z;
        g_x1[(size_t)(b*CC + c + 3)*NT + k0 + kk] = acc[q].w;
    }
}

// ------------------------- K4: graph-attn projections ----------------------
__global__ void k_gatt_proj(const float* __restrict__ W2) {
    int bn = blockIdx.x;
    int b = bn / NN, n = bn - b*NN;
    float a1[RR], a2[RR];
#pragma unroll
    for (int r = 0; r < RR; r++) { a1[r] = 0.f; a2[r] = 0.f; }
    for (int idx = threadIdx.x; idx < CT; idx += 256) {
        int c = idx / TT, t = idx - c*TT;
        float xv = g_x1[(size_t)((b*CC + c)*NN + n)*TT + t];
#pragma unroll
        for (int r = 0; r < RR; r++) {
            a1[r] += xv * g_gW1T[r*CT + idx];
            a2[r] += xv * W2[r*CT + idx];
        }
    }
    __shared__ float red[8][2*RR];
    int lane = threadIdx.x & 31, warp = threadIdx.x >> 5;
#pragma unroll
    for (int r = 0; r < RR; r++) {
#pragma unroll
        for (int off = 16; off > 0; off >>= 1) {
            a1[r] += __shfl_down_sync(0xffffffffu, a1[r], off);
            a2[r] += __shfl_down_sync(0xffffffffu, a2[r], off);
        }
    }
    if (lane == 0) {
#pragma unroll
        for (int r = 0; r < RR; r++) { red[warp][r] = a1[r]; red[warp][RR+r] = a2[r]; }
    }
    __syncthreads();
    if (threadIdx.x < 2*RR) {
        float s = 0.f;
#pragma unroll
        for (int w = 0; w < 8; w++) s += red[w][threadIdx.x];
        if (threadIdx.x < RR) g_s1g[(b*NN + n)*RR + threadIdx.x] = s;
        else                  g_s2g[(b*RR + (threadIdx.x - RR))*NN + n] = s;
    }
}

// ------------------------- K5: graph softmax * A_adj -----------------------
__global__ void k_gatt_soft(const float* __restrict__ A_adj) {
    int bi = blockIdx.x;
    int b = bi / NN, i = bi - b*NN;
    __shared__ float sc[NN];
    __shared__ float s1r[RR];
    __shared__ float red[256];
    int tid = threadIdx.x;
    if (tid < RR) s1r[tid] = g_s1g[(size_t)(b*NN + i)*RR + tid];
    __syncthreads();
    float lmax = -1e30f;
    float scale = rsqrtf((float)CT);
    for (int j = tid; j < NN; j += 256) {
        float s = 0.f;
#pragma unroll
        for (int r = 0; r < RR; r++) s += s1r[r] * g_s2g[(size_t)(b*RR + r)*NN + j];
        s *= scale;
        sc[j] = s;
        lmax = fmaxf(lmax, s);
    }
    red[tid] = lmax; __syncthreads();
    for (int off = 128; off > 0; off >>= 1) {
        if (tid < off) red[tid] = fmaxf(red[tid], red[tid + off]);
        __syncthreads();
    }
    float mx = red[0];
    __syncthreads();
    float lsum = 0.f;
    for (int j = tid; j < NN; j += 256) {
        float e = expf(sc[j] - mx);
        sc[j] = e;
        lsum += e;
    }
    red[tid] = lsum; __syncthreads();
    for (int off = 128; off > 0; off >>= 1) {
        if (tid < off) red[tid] += red[tid + off];
        __syncthreads();
    }
    float inv = 1.f / red[0];
    for (int j = tid; j < NN; j += 256) {
        g_Ag[((size_t)b*NN + i)*NN + j] = sc[j] * inv * A_adj[i*NN + j];
    }
}

// ------------------------- K6: y = x1 . gcn_W  (per (b,m) tile) ------------
__global__ void k_gcnmix(const float* __restrict__ gcn_W) {
    int bm = blockIdx.x;
    int b = bm / NN, m = bm - b*NN;
    __shared__ float xs[CC*TT];
    __shared__ float Ws[CC*CC];
    int tid = threadIdx.x;                     // 384
    for (int e = tid; e < CC*TT; e += 384) {
        int c = e / TT, t = e - c*TT;
        xs[e] = g_x1[(size_t)((b*CC + c)*NN + m)*TT + t];
    }
    for (int e = tid; e < CC*CC; e += 384) Ws[e] = gcn_W[e];
    __syncthreads();
    int og = tid / TT, t = tid - og*TT, o4 = og*4;
    float4 acc = make_float4(0.f, 0.f, 0.f, 0.f);
#pragma unroll 8
    for (int c = 0; c < CC; c++) {
        float xv = xs[c*TT + t];
        float4 w = *(const float4*)&Ws[c*CC + o4];
        acc.x += w.x * xv; acc.y += w.y * xv; acc.z += w.z * xv; acc.w += w.w * xv;
    }
    size_t base = (size_t)bm * CT;
    g_y[base + (o4 + 0)*TT + t] = acc.x;
    g_y[base + (o4 + 1)*TT + t] = acc.y;
    g_y[base + (o4 + 2)*TT + t] = acc.z;
    g_y[base + (o4 + 3)*TT + t] = acc.w;
}

// ------------------------- K7: big GEMM gb = Ag @ y  (per batch) -----------
// M=1000 (n), K=1000 (m), Ncols=1536 (o*T+t). Tile 128x64, k-tile 32, 8x4 micro.
#define GTM 128
#define GTN 64
#define GTK 32
__global__ void k_gemm() {
    int b  = blockIdx.z;
    int n0 = blockIdx.y * GTM;
    int j0 = blockIdx.x * GTN;
    const float* A  = g_Ag + (size_t)b*NN*NN;
    const float* Bm = g_y  + (size_t)b*NN*CT;
    float*       Cm = g_gb + (size_t)b*NN*CT;
    __shared__ float As[GTM][GTK + 1];
    __shared__ float Bs[GTK][GTN];
    int tid = threadIdx.x;                     // 256
    int tx = tid & 15;                         // 16 col-groups * 4
    int ty = tid >> 4;                         // 16 row-groups * 8
    float acc[8][4];
#pragma unroll
    for (int i = 0; i < 8; i++)
#pragma unroll
        for (int j = 0; j < 4; j++) acc[i][j] = 0.f;

    for (int k0 = 0; k0 < NN; k0 += GTK) {
#pragma unroll
        for (int u = 0; u < 16; u++) {         // 4096 A elems
            int e = tid + u*256;
            int kk = e & 31, nn = e >> 5;
            int n = n0 + nn, k = k0 + kk;
            As[nn][kk] = (n < NN && k < NN) ? A[(size_t)n*NN + k] : 0.f;
        }
#pragma unroll
        for (int u = 0; u < 8; u++) {          // 2048 B elems
            int e = tid + u*256;
            int jj = e & 63, kk = e >> 6;
            int k = k0 + kk;
            Bs[kk][jj] = (k < NN) ? Bm[(size_t)k*CT + j0 + jj] : 0.f;
        }
        __syncthreads();
#pragma unroll
        for (int kk = 0; kk < GTK; kk++) {
            float4 b4 = *(const float4*)&Bs[kk][tx*4];
            float av[8];
#pragma unroll
            for (int i = 0; i < 8; i++) av[i] = As[ty*8 + i][kk];
#pragma unroll
            for (int i = 0; i < 8; i++) {
                acc[i][0] += av[i] * b4.x;
                acc[i][1] += av[i] * b4.y;
                acc[i][2] += av[i] * b4.z;
                acc[i][3] += av[i] * b4.w;
            }
        }
        __syncthreads();
    }
#pragma unroll
    for (int i = 0; i < 8; i++) {
        int n = n0 + ty*8 + i;
        if (n < NN) {
            float4 v = make_float4(acc[i][0], acc[i][1], acc[i][2], acc[i][3]);
            *(float4*)&Cm[(size_t)n*CT + j0 + tx*4] = v;
        }
    }
}

// ------------------------- K8: temporal-attn projections -------------------
__global__ void k_tatt_proj(const float* __restrict__ W2) {
    int bt = blockIdx.x;                       // b*24 + t
    int b = bt / TT, t = bt - b*TT;
    float a1[RR], a2[RR];
#pragma unroll
    for (int r = 0; r < RR; r++) { a1[r] = 0.f; a2[r] = 0.f; }
    for (int idx = threadIdx.x; idx < NCO; idx += 256) {
        int n = idx >> 6, o = idx & 63;
        float gv = g_gb[(size_t)(b*NN + n)*CT + o*TT + t];
#pragma unroll
        for (int r = 0; r < RR; r++) {
            a1[r] += gv * g_tW1T[r*NCO + idx];
            a2[r] += gv * W2[r*NCO + idx];
        }
    }
    __shared__ float red[8][2*RR];
    int lane = threadIdx.x & 31, warp = threadIdx.x >> 5;
#pragma unroll
    for (int r = 0; r < RR; r++) {
#pragma unroll
        for (int off = 16; off > 0; off >>= 1) {
            a1[r] += __shfl_down_sync(0xffffffffu, a1[r], off);
            a2[r] += __shfl_down_sync(0xffffffffu, a2[r], off);
        }
    }
    if (lane == 0) {
#pragma unroll
        for (int r = 0; r < RR; r++) { red[warp][r] = a1[r]; red[warp][RR+r] = a2[r]; }
    }
    __syncthreads();
    if (threadIdx.x < 2*RR) {
        float s = 0.f;
#pragma unroll
        for (int w = 0; w < 8; w++) s += red[w][threadIdx.x];
        if (threadIdx.x < RR) g_s1t[(b*TT + t)*RR + threadIdx.x] = s;
        else                  g_s2t[(b*RR + (threadIdx.x - RR))*TT + t] = s;
    }
}

// ------------------------- K9: temporal softmax (24x24) --------------------
__global__ void k_tatt_soft() {
    int b = blockIdx.x;
    int i = threadIdx.x;
    if (i >= TT) return;
    float sc[TT];
    float scale = rsqrtf((float)NCO);
#pragma unroll
    for (int j = 0; j < TT; j++) {
        float s = 0.f;
#pragma unroll
        for (int r = 0; r < RR; r++) s += g_s1t[(b*TT + i)*RR + r] * g_s2t[(b*RR + r)*TT + j];
        sc[j] = s * scale;
    }
    float mx = -1e30f;
#pragma unroll
    for (int j = 0; j < TT; j++) mx = fmaxf(mx, sc[j]);
    float sum = 0.f;
#pragma unroll
    for (int j = 0; j < TT; j++) { sc[j] = expf(sc[j] - mx); sum += sc[j]; }
    float inv = 1.f / sum;
#pragma unroll
    for (int j = 0; j < TT; j++) g_attT[(b*TT + i)*TT + j] = sc[j] * inv;
}

// ------------------------- K10: fused TCN-apply + convs + res + LN ---------
// per (b,n): x2 = attT @ g; conv1(d=1)+relu; conv2(d=2)+relu; +res(1x1)+relu; LN over Co.
__global__ void k_final(const float* __restrict__ x,
                        const float* __restrict__ c1b,
                        const float* __restrict__ c2b,
                        const float* __restrict__ rb,
                        const float* __restrict__ lng,
                        const float* __restrict__ lnb,
                        float* __restrict__ out) {
    int bn = blockIdx.x;
    int b = bn / NN, n = bn - b*NN;
    __shared__ float gt[CT];
    __shared__ float at[TT*TT];
    __shared__ float xa[CT];
    __shared__ float xb[CT];
    __shared__ float xt[CT];
    __shared__ float ps[TT][16];
    __shared__ float pq[TT][16];
    __shared__ float mus[TT], rsg[TT];
    int tid = threadIdx.x;                     // 384
    for (int e = tid; e < CT; e += 384) gt[e] = g_gb[(size_t)bn*CT + e];
    for (int e = tid; e < TT*TT; e += 384) at[e] = g_attT[b*TT*TT + e];
    for (int e = tid; e < CT; e += 384) {
        int c = e / TT, t = e - c*TT;
        xt[e] = x[(size_t)((b*CC + c)*NN + n)*TT + t];
    }
    __syncthreads();
    int og = tid / TT, t = tid - og*TT, o4 = og*4;

    // temporal attention apply: x2[o][t] = sum_t' attT[t][t'] * g[o][t']
    float4 a4 = make_float4(0.f, 0.f, 0.f, 0.f);
#pragma unroll
    for (int tp = 0; tp < TT; tp++) {
        float av = at[t*TT + tp];
        a4.x += av * gt[(o4 + 0)*TT + tp];
        a4.y += av * gt[(o4 + 1)*TT + tp];
        a4.z += av * gt[(o4 + 2)*TT + tp];
        a4.w += av * gt[(o4 + 3)*TT + tp];
    }
    xa[(o4 + 0)*TT + t] = a4.x;
    xa[(o4 + 1)*TT + t] = a4.y;
    xa[(o4 + 2)*TT + t] = a4.z;
    xa[(o4 + 3)*TT + t] = a4.w;
    __syncthreads();

    // conv1, dilation 1: y[t] = b + sum_c w0[c][o]*x[t-1] + w1[c][o]*x[t]
    {
        float4 acc = __ldg((const float4*)(c1b + o4));
#pragma unroll 8
        for (int c = 0; c < CC; c++) {
            float x0 = (t >= 1) ? xa[c*TT + t - 1] : 0.f;
            float x1v = xa[c*TT + t];
            float4 w0 = __ldg((const float4*)(g_w1T + c*CC + o4));
            float4 w1 = __ldg((const float4*)(g_w1T + CC*CC + c*CC + o4));
            acc.x += w0.x*x0 + w1.x*x1v;
            acc.y += w0.y*x0 + w1.y*x1v;
            acc.z += w0.z*x0 + w1.z*x1v;
            acc.w += w0.w*x0 + w1.w*x1v;
        }
        xb[(o4 + 0)*TT + t] = fmaxf(acc.x, 0.f);
        xb[(o4 + 1)*TT + t] = fmaxf(acc.y, 0.f);
        xb[(o4 + 2)*TT + t] = fmaxf(acc.z, 0.f);
        xb[(o4 + 3)*TT + t] = fmaxf(acc.w, 0.f);
    }
    __syncthreads();

    // conv2, dilation 2 -> keep in regs
    float v[4];
    {
        float4 acc = __ldg((const float4*)(c2b + o4));
#pragma unroll 8
        for (int c = 0; c < CC; c++) {
            float x0 = (t >= 2) ? xb[c*TT + t - 2] : 0.f;
            float x1v = xb[c*TT + t];
            float4 w0 = __ldg((const float4*)(g_w2T + c*CC + o4));
            float4 w1 = __ldg((const float4*)(g_w2T + CC*CC + c*CC + o4));
            acc.x += w0.x*x0 + w1.x*x1v;
            acc.y += w0.y*x0 + w1.y*x1v;
            acc.z += w0.z*x0 + w1.z*x1v;
            acc.w += w0.w*x0 + w1.w*x1v;
        }
        v[0] = fmaxf(acc.x, 0.f);
        v[1] = fmaxf(acc.y, 0.f);
        v[2] = fmaxf(acc.z, 0.f);
        v[3] = fmaxf(acc.w, 0.f);
    }

    // residual 1x1 on original x, then relu(x2 + res)
    {
        float4 acc = __ldg((const float4*)(rb + o4));
#pragma unroll 8
        for (int c = 0; c < CC; c++) {
            float xv = xt[c*TT + t];
            float4 rw = __ldg((const float4*)(g_rT + c*CC + o4));
            acc.x += rw.x*xv; acc.y += rw.y*xv; acc.z += rw.z*xv; acc.w += rw.w*xv;
        }
        v[0] = fmaxf(v[0] + acc.x, 0.f);
        v[1] = fmaxf(v[1] + acc.y, 0.f);
        v[2] = fmaxf(v[2] + acc.z, 0.f);
        v[3] = fmaxf(v[3] + acc.w, 0.f);
    }

    // LayerNorm over channel (64) per t
    float s = v[0] + v[1] + v[2] + v[3];
    float q = v[0]*v[0] + v[1]*v[1] + v[2]*v[2] + v[3]*v[3];
    ps[t][og] = s; pq[t][og] = q;
    __syncthreads();
    if (tid < TT) {
        float S = 0.f, Q = 0.f;
#pragma unroll
        for (int g2 = 0; g2 < 16; g2++) { S += ps[tid][g2]; Q += pq[tid][g2]; }
        float mu = S * (1.f/CC);
        float var = Q * (1.f/CC) - mu*mu;
        mus[tid] = mu;
        rsg[tid] = rsqrtf(var + 1e-5f);
    }
    __syncthreads();
    float mu = mus[t], rs = rsg[t];
#pragma unroll
    for (int i = 0; i < 4; i++) {
        int o = o4 + i;
        out[(size_t)((b*CC + o)*NN + n)*TT + t] =
            (v[i] - mu) * rs * __ldg(lng + o) + __ldg(lnb + o);
    }
}

// ------------------------- launch ------------------------------------------
extern "C" void kernel_launch(void* const* d_in, const int* in_sizes, int n_in,
                              void* d_out, int out_size) {
    const float* x     = (const float*)d_in[0];
    const float* A_adj = (const float*)d_in[1];
    const float* a0W1  = (const float*)d_in[2];
    const float* a0W2  = (const float*)d_in[3];
    const float* gW1   = (const float*)d_in[4];
    const float* gW2   = (const float*)d_in[5];
    const float* gcnW  = (const float*)d_in[6];
    const float* tW1   = (const float*)d_in[7];
    const float* tW2   = (const float*)d_in[8];
    const float* c1w   = (const float*)d_in[9];
    const float* c1b   = (const float*)d_in[10];
    const float* c2w   = (const float*)d_in[11];
    const float* c2b   = (const float*)d_in[12];
    const float* resw  = (const float*)d_in[13];
    const float* resb  = (const float*)d_in[14];
    const float* lng   = (const float*)d_in[15];
    const float* lnb   = (const float*)d_in[16];
    float* out = (float*)d_out;

    k_prep<<<3514, 256>>>(a0W1, gW1, tW1, c1w, c2w, resw);
    k_attA_proj<<<BB*CC, 256>>>(x, a0W2);
    k_attA_soft<<<BB*CC, CC>>>();
    k_chan_apply<<<dim3(NT/64, BB), 256>>>(x);
    k_gatt_proj<<<BB*NN, 256>>>(gW2);
    k_gatt_soft<<<BB*NN, 256>>>(A_adj);
    k_gcnmix<<<BB*NN, 384>>>(gcnW);
    k_gemm<<<dim3(CT/GTN, (NN + GTM - 1)/GTM, BB), 256>>>();
    k_tatt_proj<<<BB*TT, 256>>>(tW2);
    k_tatt_soft<<<BB, 32>>>();
    k_final<<<BB*NN, 384>>>(x, c1b, c2b, resb, lng, lnb, out);
}

// round 3
// speedup vs baseline: 1.4141x; 1.4141x over previous
#include <cuda_runtime.h>
#include <math.h>

#define BB 8
#define CC 64
#define NN 1000
#define TT 24
#define RR 10
#define NT 24000     // NN*TT
#define CT 1536      // CC*TT
#define NCO 64000    // NN*CC

// ------------------------- scratch (device globals, no allocs) -------------
__device__ float g_x1[BB*CC*NT];          // x1 [b,c,n,t]
__device__ float g_s1a[BB*CC*RR];
__device__ float g_s2a[BB*RR*CC];
__device__ float g_att0[BB*CC*CC];
__device__ float g_s1g[BB*NN*RR];
__device__ float g_s2g[BB*RR*NN];
__device__ float g_Ag[BB*NN*NN];          // gated adjacency [b,n,m]
__device__ float g_y[BB*NN*CT];           // (x1 . gcn_W)  [b,m,(o*T+t)]
__device__ float g_gb[BB*NN*CT];          // g             [b,n,(o*T+t)]
__device__ float g_s1t[BB*TT*RR];
__device__ float g_s2t[BB*RR*TT];
__device__ float g_attT[BB*TT*TT];
// transposed weights
__device__ float g_a0W1T[RR*NT];
__device__ float g_gW1T[RR*CT];
__device__ float g_tW1T[RR*NCO];
__device__ float g_w1T[2*CC*CC];          // conv1 [tap][c][o]
__device__ float g_w2T[2*CC*CC];          // conv2 [tap][c][o]
__device__ float g_rT[CC*CC];             // res_w [c][o]

// ------------------------- K0: weight prep (transposes) --------------------
__global__ void k_prep(const float* __restrict__ a0W1, const float* __restrict__ gW1,
                       const float* __restrict__ tW1, const float* __restrict__ c1w,
                       const float* __restrict__ c2w, const float* __restrict__ rw) {
    int e = blockIdx.x * 256 + threadIdx.x;
    if (e < NT*RR)  { int k = e/RR, r = e - k*RR; g_a0W1T[r*NT + k] = a0W1[e]; return; }
    e -= NT*RR;
    if (e < CT*RR)  { int k = e/RR, r = e - k*RR; g_gW1T[r*CT + k] = gW1[e]; return; }
    e -= CT*RR;
    if (e < NCO*RR) { int k = e/RR, r = e - k*RR; g_tW1T[r*NCO + k] = tW1[e]; return; }
    e -= NCO*RR;
    if (e < CC*CC) {
        int o = e >> 6, c = e & 63;
        g_w1T[c*CC + o]         = c1w[e*2 + 0];
        g_w1T[CC*CC + c*CC + o] = c1w[e*2 + 1];
        g_w2T[c*CC + o]         = c2w[e*2 + 0];
        g_w2T[CC*CC + c*CC + o] = c2w[e*2 + 1];
        g_rT[c*CC + o]          = rw[e];
    }
}

// ------------------------- K1: channel-attn projections --------------------
// s1[b,c,r] = sum_k xf[b,c,k]*W1[k,r];  s2[b,r,c] = sum_k W2[r,k]*xf[b,c,k]
__global__ void k_attA_proj(const float* __restrict__ x, const float* __restrict__ W2) {
    int bc = blockIdx.x;                       // b*64 + c
    const float* xf = x + (size_t)bc * NT;
    float a1[RR], a2[RR];
#pragma unroll
    for (int r = 0; r < RR; r++) { a1[r] = 0.f; a2[r] = 0.f; }
    for (int k = threadIdx.x; k < NT; k += 256) {
        float xv = xf[k];
#pragma unroll
        for (int r = 0; r < RR; r++) {
            a1[r] += xv * g_a0W1T[r*NT + k];
            a2[r] += xv * W2[r*NT + k];
        }
    }
    __shared__ float red[8][2*RR];
    int lane = threadIdx.x & 31, warp = threadIdx.x >> 5;
#pragma unroll
    for (int r = 0; r < RR; r++) {
#pragma unroll
        for (int off = 16; off > 0; off >>= 1) {
            a1[r] += __shfl_down_sync(0xffffffffu, a1[r], off);
            a2[r] += __shfl_down_sync(0xffffffffu, a2[r], off);
        }
    }
    if (lane == 0) {
#pragma unroll
        for (int r = 0; r < RR; r++) { red[warp][r] = a1[r]; red[warp][RR+r] = a2[r]; }
    }
    __syncthreads();
    if (threadIdx.x < 2*RR) {
        float s = 0.f;
#pragma unroll
        for (int w = 0; w < 8; w++) s += red[w][threadIdx.x];
        int b = bc >> 6, c = bc & 63;
        if (threadIdx.x < RR) g_s1a[(b*CC + c)*RR + threadIdx.x] = s;
        else                  g_s2a[(b*RR + (threadIdx.x - RR))*CC + c] = s;
    }
}

// ------------------------- K2: channel-attn softmax (64x64) ----------------
__global__ void k_attA_soft() {
    int b = blockIdx.x >> 6, i = blockIdx.x & 63;
    int j = threadIdx.x;                       // 64 threads
    float s = 0.f;
#pragma unroll
    for (int r = 0; r < RR; r++) s += g_s1a[(b*CC + i)*RR + r] * g_s2a[(b*RR + r)*CC + j];
    s *= rsqrtf((float)NT);
    __shared__ float sm[CC];
    sm[j] = s; __syncthreads();
    float mx = -1e30f;
    for (int jj = 0; jj < CC; jj++) mx = fmaxf(mx, sm[jj]);
    float e = expf(s - mx);
    __syncthreads();
    sm[j] = e; __syncthreads();
    float sum = 0.f;
    for (int jj = 0; jj < CC; jj++) sum += sm[jj];
    g_att0[(b*CC + i)*CC + j] = e / sum;
}

// ------------------------- K3: x1 = att0 @ xf -------------------------------
__global__ void k_chan_apply(const float* __restrict__ x) {
    int b = blockIdx.y;
    int k0 = blockIdx.x * 64;
    __shared__ float attsT[CC][68];            // [j][c], padded
    __shared__ float xfs[CC][64];              // [j][kk]
    int tid = threadIdx.x;                     // 256
    for (int e = tid; e < CC*CC; e += 256) {
        int c = e >> 6, j = e & 63;
        attsT[j][c] = g_att0[b*CC*CC + e];
    }
    for (int e = tid; e < CC*64; e += 256) {
        int j = e >> 6, kk = e & 63;
        xfs[j][kk] = x[(size_t)(b*CC + j)*NT + k0 + kk];
    }
    __syncthreads();
    int kk = tid & 63, cg = tid >> 6;          // cg: 0..3 -> 16 c's each
    float4 acc[4];
#pragma unroll
    for (int q = 0; q < 4; q++) acc[q] = make_float4(0.f, 0.f, 0.f, 0.f);
    for (int j = 0; j < CC; j++) {
        float xv = xfs[j][kk];
        const float4* ap = (const float4*)&attsT[j][cg*16];
#pragma unroll
        for (int q = 0; q < 4; q++) {
            float4 a = ap[q];
            acc[q].x += a.x * xv; acc[q].y += a.y * xv;
            acc[q].z += a.z * xv; acc[q].w += a.w * xv;
        }
    }
#pragma unroll
    for (int q = 0; q < 4; q++) {
        int c = cg*16 + q*4;
        g_x1[(size_t)(b*CC + c + 0)*NT + k0 + kk] = acc[q].x;
        g_x1[(size_t)(b*CC + c + 1)*NT + k0 + kk] = acc[q].y;
        g_x1[(size_t)(b*CC + c + 2)*NT + k0 + kk] = acc[q].z;
        g_x1[(size_t)(b*CC + c + 3)*NT + k0 + kk] = acc[q].w;
    }
}

// ------------------------- K4: graph-attn projections ----------------------
__global__ void k_gatt_proj(const float* __restrict__ W2) {
    int bn = blockIdx.x;
    int b = bn / NN, n = bn - b*NN;
    float a1[RR], a2[RR];
#pragma unroll
    for (int r = 0; r < RR; r++) { a1[r] = 0.f; a2[r] = 0.f; }
    for (int idx = threadIdx.x; idx < CT; idx += 256) {
        int c = idx / TT, t = idx - c*TT;
        float xv = g_x1[(size_t)((b*CC + c)*NN + n)*TT + t];
#pragma unroll
        for (int r = 0; r < RR; r++) {
            a1[r] += xv * g_gW1T[r*CT + idx];
            a2[r] += xv * W2[r*CT + idx];
        }
    }
    __shared__ float red[8][2*RR];
    int lane = threadIdx.x & 31, warp = threadIdx.x >> 5;
#pragma unroll
    for (int r = 0; r < RR; r++) {
#pragma unroll
        for (int off = 16; off > 0; off >>= 1) {
            a1[r] += __shfl_down_sync(0xffffffffu, a1[r], off);
            a2[r] += __shfl_down_sync(0xffffffffu, a2[r], off);
        }
    }
    if (lane == 0) {
#pragma unroll
        for (int r = 0; r < RR; r++) { red[warp][r] = a1[r]; red[warp][RR+r] = a2[r]; }
    }
    __syncthreads();
    if (threadIdx.x < 2*RR) {
        float s = 0.f;
#pragma unroll
        for (int w = 0; w < 8; w++) s += red[w][threadIdx.x];
        if (threadIdx.x < RR) g_s1g[(b*NN + n)*RR + threadIdx.x] = s;
        else                  g_s2g[(b*RR + (threadIdx.x - RR))*NN + n] = s;
    }
}

// ------------------------- K5: graph softmax * A_adj -----------------------
__global__ void k_gatt_soft(const float* __restrict__ A_adj) {
    int bi = blockIdx.x;
    int b = bi / NN, i = bi - b*NN;
    __shared__ float sc[NN];
    __shared__ float s1r[RR];
    __shared__ float red[256];
    int tid = threadIdx.x;
    if (tid < RR) s1r[tid] = g_s1g[(size_t)(b*NN + i)*RR + tid];
    __syncthreads();
    float lmax = -1e30f;
    float scale = rsqrtf((float)CT);
    for (int j = tid; j < NN; j += 256) {
        float s = 0.f;
#pragma unroll
        for (int r = 0; r < RR; r++) s += s1r[r] * g_s2g[(size_t)(b*RR + r)*NN + j];
        s *= scale;
        sc[j] = s;
        lmax = fmaxf(lmax, s);
    }
    red[tid] = lmax; __syncthreads();
    for (int off = 128; off > 0; off >>= 1) {
        if (tid < off) red[tid] = fmaxf(red[tid], red[tid + off]);
        __syncthreads();
    }
    float mx = red[0];
    __syncthreads();
    float lsum = 0.f;
    for (int j = tid; j < NN; j += 256) {
        float e = expf(sc[j] - mx);
        sc[j] = e;
        lsum += e;
    }
    red[tid] = lsum; __syncthreads();
    for (int off = 128; off > 0; off >>= 1) {
        if (tid < off) red[tid] += red[tid + off];
        __syncthreads();
    }
    float inv = 1.f / red[0];
    for (int j = tid; j < NN; j += 256) {
        g_Ag[((size_t)b*NN + i)*NN + j] = sc[j] * inv * A_adj[i*NN + j];
    }
}

// ------------------------- K6: y = x1 . gcn_W  (per (b,m) tile) ------------
__global__ void k_gcnmix(const float* __restrict__ gcn_W) {
    int bm = blockIdx.x;
    int b = bm / NN, m = bm - b*NN;
    __shared__ float xs[CC*TT];
    __shared__ float Ws[CC*CC];
    int tid = threadIdx.x;                     // 384
    for (int e = tid; e < CC*TT; e += 384) {
        int c = e / TT, t = e - c*TT;
        xs[e] = g_x1[(size_t)((b*CC + c)*NN + m)*TT + t];
    }
    for (int e = tid; e < CC*CC; e += 384) Ws[e] = gcn_W[e];
    __syncthreads();
    int og = tid / TT, t = tid - og*TT, o4 = og*4;
    float4 acc = make_float4(0.f, 0.f, 0.f, 0.f);
#pragma unroll 8
    for (int c = 0; c < CC; c++) {
        float xv = xs[c*TT + t];
        float4 w = *(const float4*)&Ws[c*CC + o4];
        acc.x += w.x * xv; acc.y += w.y * xv; acc.z += w.z * xv; acc.w += w.w * xv;
    }
    size_t base = (size_t)bm * CT;
    g_y[base + (o4 + 0)*TT + t] = acc.x;
    g_y[base + (o4 + 1)*TT + t] = acc.y;
    g_y[base + (o4 + 2)*TT + t] = acc.z;
    g_y[base + (o4 + 3)*TT + t] = acc.w;
}

// ------------------------- K7: big GEMM gb = Ag @ y  (per batch) -----------
// M=1000 (n), K=1000 (m), Ncols=1536 (o*T+t). Tile 128x64, k-tile 32, 8x4 micro.
#define GTM 128
#define GTN 64
#define GTK 32
__global__ void k_gemm() {
    int b  = blockIdx.z;
    int n0 = blockIdx.y * GTM;
    int j0 = blockIdx.x * GTN;
    const float* A  = g_Ag + (size_t)b*NN*NN;
    const float* Bm = g_y  + (size_t)b*NN*CT;
    float*       Cm = g_gb + (size_t)b*NN*CT;
    __shared__ float As[GTM][GTK + 1];
    __shared__ float Bs[GTK][GTN];
    int tid = threadIdx.x;                     // 256
    int tx = tid & 15;                         // 16 col-groups * 4
    int ty = tid >> 4;                         // 16 row-groups * 8
    float acc[8][4];
#pragma unroll
    for (int i = 0; i < 8; i++)
#pragma unroll
        for (int j = 0; j < 4; j++) acc[i][j] = 0.f;

    for (int k0 = 0; k0 < NN; k0 += GTK) {
#pragma unroll
        for (int u = 0; u < 16; u++) {         // 4096 A elems
            int e = tid + u*256;
            int kk = e & 31, nn = e >> 5;
            int n = n0 + nn, k = k0 + kk;
            As[nn][kk] = (n < NN && k < NN) ? A[(size_t)n*NN + k] : 0.f;
        }
#pragma unroll
        for (int u = 0; u < 8; u++) {          // 2048 B elems
            int e = tid + u*256;
            int jj = e & 63, kk = e >> 6;
            int k = k0 + kk;
            Bs[kk][jj] = (k < NN) ? Bm[(size_t)k*CT + j0 + jj] : 0.f;
        }
        __syncthreads();
#pragma unroll
        for (int kk = 0; kk < GTK; kk++) {
            float4 b4 = *(const float4*)&Bs[kk][tx*4];
            float av[8];
#pragma unroll
            for (int i = 0; i < 8; i++) av[i] = As[ty*8 + i][kk];
#pragma unroll
            for (int i = 0; i < 8; i++) {
                acc[i][0] += av[i] * b4.x;
                acc[i][1] += av[i] * b4.y;
                acc[i][2] += av[i] * b4.z;
                acc[i][3] += av[i] * b4.w;
            }
        }
        __syncthreads();
    }
#pragma unroll
    for (int i = 0; i < 8; i++) {
        int n = n0 + ty*8 + i;
        if (n < NN) {
            float4 v = make_float4(acc[i][0], acc[i][1], acc[i][2], acc[i][3]);
            *(float4*)&Cm[(size_t)n*CT + j0 + tx*4] = v;
        }
    }
}

// ------------------------- K8: temporal-attn projections -------------------
__global__ void k_tatt_proj(const float* __restrict__ W2) {
    int bt = blockIdx.x;                       // b*24 + t
    int b = bt / TT, t = bt - b*TT;
    float a1[RR], a2[RR];
#pragma unroll
    for (int r = 0; r < RR; r++) { a1[r] = 0.f; a2[r] = 0.f; }
    for (int idx = threadIdx.x; idx < NCO; idx += 256) {
        int n = idx >> 6, o = idx & 63;
        float gv = g_gb[(size_t)(b*NN + n)*CT + o*TT + t];
#pragma unroll
        for (int r = 0; r < RR; r++) {
            a1[r] += gv * g_tW1T[r*NCO + idx];
            a2[r] += gv * W2[r*NCO + idx];
        }
    }
    __shared__ float red[8][2*RR];
    int lane = threadIdx.x & 31, warp = threadIdx.x >> 5;
#pragma unroll
    for (int r = 0; r < RR; r++) {
#pragma unroll
        for (int off = 16; off > 0; off >>= 1) {
            a1[r] += __shfl_down_sync(0xffffffffu, a1[r], off);
            a2[r] += __shfl_down_sync(0xffffffffu, a2[r], off);
        }
    }
    if (lane == 0) {
#pragma unroll
        for (int r = 0; r < RR; r++) { red[warp][r] = a1[r]; red[warp][RR+r] = a2[r]; }
    }
    __syncthreads();
    if (threadIdx.x < 2*RR) {
        float s = 0.f;
#pragma unroll
        for (int w = 0; w < 8; w++) s += red[w][threadIdx.x];
        if (threadIdx.x < RR) g_s1t[(b*TT + t)*RR + threadIdx.x] = s;
        else                  g_s2t[(b*RR + (threadIdx.x - RR))*TT + t] = s;
    }
}

// ------------------------- K9: temporal softmax (24x24) --------------------
__global__ void k_tatt_soft() {
    int b = blockIdx.x;
    int i = threadIdx.x;
    if (i >= TT) return;
    float sc[TT];
    float scale = rsqrtf((float)NCO);
#pragma unroll
    for (int j = 0; j < TT; j++) {
        float s = 0.f;
#pragma unroll
        for (int r = 0; r < RR; r++) s += g_s1t[(b*TT + i)*RR + r] * g_s2t[(b*RR + r)*TT + j];
        sc[j] = s * scale;
    }
    float mx = -1e30f;
#pragma unroll
    for (int j = 0; j < TT; j++) mx = fmaxf(mx, sc[j]);
    float sum = 0.f;
#pragma unroll
    for (int j = 0; j < TT; j++) { sc[j] = expf(sc[j] - mx); sum += sc[j]; }
    float inv = 1.f / sum;
#pragma unroll
    for (int j = 0; j < TT; j++) g_attT[(b*TT + i)*TT + j] = sc[j] * inv;
}

// ------------------------- K10: fused TCN-apply + convs + res + LN ---------
// per (b,n): x2 = attT @ g; conv1(d=1)+relu; conv2(d=2)+relu; +res(1x1)+relu; LN over Co.
__global__ void k_final(const float* __restrict__ x,
                        const float* __restrict__ c1b,
                        const float* __restrict__ c2b,
                        const float* __restrict__ rb,
                        const float* __restrict__ lng,
                        const float* __restrict__ lnb,
                        float* __restrict__ out) {
    int bn = blockIdx.x;
    int b = bn / NN, n = bn - b*NN;
    __shared__ float gt[CT];
    __shared__ float at[TT*TT];
    __shared__ float xa[CT];
    __shared__ float xb[CT];
    __shared__ float xt[CT];
    __shared__ float ps[TT][16];
    __shared__ float pq[TT][16];
    __shared__ float mus[TT], rsg[TT];
    int tid = threadIdx.x;                     // 384
    for (int e = tid; e < CT; e += 384) gt[e] = g_gb[(size_t)bn*CT + e];
    for (int e = tid; e < TT*TT; e += 384) at[e] = g_attT[b*TT*TT + e];
    for (int e = tid; e < CT; e += 384) {
        int c = e / TT, t = e - c*TT;
        xt[e] = x[(size_t)((b*CC + c)*NN + n)*TT + t];
    }
    __syncthreads();
    int og = tid / TT, t = tid - og*TT, o4 = og*4;

    // temporal attention apply: x2[o][t] = sum_t' attT[t][t'] * g[o][t']
    float4 a4 = make_float4(0.f, 0.f, 0.f, 0.f);
#pragma unroll
    for (int tp = 0; tp < TT; tp++) {
        float av = at[t*TT + tp];
        a4.x += av * gt[(o4 + 0)*TT + tp];
        a4.y += av * gt[(o4 + 1)*TT + tp];
        a4.z += av * gt[(o4 + 2)*TT + tp];
        a4.w += av * gt[(o4 + 3)*TT + tp];
    }
    xa[(o4 + 0)*TT + t] = a4.x;
    xa[(o4 + 1)*TT + t] = a4.y;
    xa[(o4 + 2)*TT + t] = a4.z;
    xa[(o4 + 3)*TT + t] = a4.w;
    __syncthreads();

    // conv1, dilation 1: y[t] = b + sum_c w0[c][o]*x[t-1] + w1[c][o]*x[t]
    {
        float4 acc = __ldg((const float4*)(c1b + o4));
#pragma unroll 8
        for (int c = 0; c < CC; c++) {
            float x0 = (t >= 1) ? xa[c*TT + t - 1] : 0.f;
            float x1v = xa[c*TT + t];
            float4 w0 = __ldg((const float4*)(g_w1T + c*CC + o4));
            float4 w1 = __ldg((const float4*)(g_w1T + CC*CC + c*CC + o4));
            acc.x += w0.x*x0 + w1.x*x1v;
            acc.y += w0.y*x0 + w1.y*x1v;
            acc.z += w0.z*x0 + w1.z*x1v;
            acc.w += w0.w*x0 + w1.w*x1v;
        }
        xb[(o4 + 0)*TT + t] = fmaxf(acc.x, 0.f);
        xb[(o4 + 1)*TT + t] = fmaxf(acc.y, 0.f);
        xb[(o4 + 2)*TT + t] = fmaxf(acc.z, 0.f);
        xb[(o4 + 3)*TT + t] = fmaxf(acc.w, 0.f);
    }
    __syncthreads();

    // conv2, dilation 2 -> keep in regs
    float v[4];
    {
        float4 acc = __ldg((const float4*)(c2b + o4));
#pragma unroll 8
        for (int c = 0; c < CC; c++) {
            float x0 = (t >= 2) ? xb[c*TT + t - 2] : 0.f;
            float x1v = xb[c*TT + t];
            float4 w0 = __ldg((const float4*)(g_w2T + c*CC + o4));
            float4 w1 = __ldg((const float4*)(g_w2T + CC*CC + c*CC + o4));
            acc.x += w0.x*x0 + w1.x*x1v;
            acc.y += w0.y*x0 + w1.y*x1v;
            acc.z += w0.z*x0 + w1.z*x1v;
            acc.w += w0.w*x0 + w1.w*x1v;
        }
        v[0] = fmaxf(acc.x, 0.f);
        v[1] = fmaxf(acc.y, 0.f);
        v[2] = fmaxf(acc.z, 0.f);
        v[3] = fmaxf(acc.w, 0.f);
    }

    // residual 1x1 on original x, then relu(x2 + res)
    {
        float4 acc = __ldg((const float4*)(rb + o4));
#pragma unroll 8
        for (int c = 0; c < CC; c++) {
            float xv = xt[c*TT + t];
            float4 rw = __ldg((const float4*)(g_rT + c*CC + o4));
            acc.x += rw.x*xv; acc.y += rw.y*xv; acc.z += rw.z*xv; acc.w += rw.w*xv;
        }
        v[0] = fmaxf(v[0] + acc.x, 0.f);
        v[1] = fmaxf(v[1] + acc.y, 0.f);
        v[2] = fmaxf(v[2] + acc.z, 0.f);
        v[3] = fmaxf(v[3] + acc.w, 0.f);
    }

    // LayerNorm over channel (64) per t
    float s = v[0] + v[1] + v[2] + v[3];
    float q = v[0]*v[0] + v[1]*v[1] + v[2]*v[2] + v[3]*v[3];
    ps[t][og] = s; pq[t][og] = q;
    __syncthreads();
    if (tid < TT) {
        float S = 0.f, Q = 0.f;
#pragma unroll
        for (int g2 = 0; g2 < 16; g2++) { S += ps[tid][g2]; Q += pq[tid][g2]; }
        float mu = S * (1.f/CC);
        float var = Q * (1.f/CC) - mu*mu;
        mus[tid] = mu;
        rsg[tid] = rsqrtf(var + 1e-5f);
    }
    __syncthreads();
    float mu = mus[t], rs = rsg[t];
#pragma unroll
    for (int i = 0; i < 4; i++) {
        int o = o4 + i;
        out[(size_t)((b*CC + o)*NN + n)*TT + t] =
            (v[i] - mu) * rs * __ldg(lng + o) + __ldg(lnb + o);
    }
}

// ------------------------- launch ------------------------------------------
extern "C" void kernel_launch(void* const* d_in, const int* in_sizes, int n_in,
                              void* d_out, int out_size) {
    const float* x     = (const float*)d_in[0];
    const float* A_adj = (const float*)d_in[1];
    const float* a0W1  = (const float*)d_in[2];
    const float* a0W2  = (const float*)d_in[3];
    const float* gW1   = (const float*)d_in[4];
    const float* gW2   = (const float*)d_in[5];
    const float* gcnW  = (const float*)d_in[6];
    const float* tW1   = (const float*)d_in[7];
    const float* tW2   = (const float*)d_in[8];
    const float* c1w   = (const float*)d_in[9];
    const float* c1b   = (const float*)d_in[10];
    const float* c2w   = (const float*)d_in[11];
    const float* c2b   = (const float*)d_in[12];
    const float* resw  = (const float*)d_in[13];
    const float* resb  = (const float*)d_in[14];
    const float* lng   = (const float*)d_in[15];
    const float* lnb   = (const float*)d_in[16];
    float* out = (float*)d_out;

    k_prep<<<3514, 256>>>(a0W1, gW1, tW1, c1w, c2w, resw);
    k_attA_proj<<<BB*CC, 256>>>(x, a0W2);
    k_attA_soft<<<BB*CC, CC>>>();
    k_chan_apply<<<dim3(NT/64, BB), 256>>>(x);
    k_gatt_proj<<<BB*NN, 256>>>(gW2);
    k_gatt_soft<<<BB*NN, 256>>>(A_adj);
    k_gcnmix<<<BB*NN, 384>>>(gcnW);
    k_gemm<<<dim3(CT/GTN, (NN + GTM - 1)/GTM, BB), 256>>>();
    k_tatt_proj<<<BB*TT, 256>>>(tW2);
    k_tatt_soft<<<BB, 32>>>();
    k_final<<<BB*NN, 384>>>(x, c1b, c2b, resb, lng, lnb, out);
}

// round 4
// speedup vs baseline: 1.4946x; 1.0569x over previous
#include <cuda_runtime.h>
#include <math.h>

#define BB 8
#define CC 64
#define NN 1000
#define TT 24
#define RR 10
#define NT 24000     // NN*TT
#define CT 1536      // CC*TT
#define NCO 64000    // NN*CC

// ------------------------- scratch (device globals, no allocs) -------------
__device__ float g_x1[BB*CC*NT];          // x1 [b,c,n,t]
__device__ float g_s1a[BB*CC*RR];
__device__ float g_s2a[BB*RR*CC];
__device__ float g_att0[BB*CC*CC];
__device__ float g_s1g[BB*NN*RR];
__device__ float g_s2g[BB*RR*NN];
__device__ float g_Ag[BB*NN*NN];          // gated adjacency [b,n,m]
__device__ float g_y[BB*NN*CT];           // (x1 . gcn_W)  [b,m,(o*T+t)]
__device__ float g_gb[BB*NN*CT];          // g             [b,n,(o*T+t)]
__device__ float g_s1t[BB*TT*RR];
__device__ float g_s2t[BB*RR*TT];
__device__ float g_attT[BB*TT*TT];
// transposed weights
__device__ float g_a0W1T[RR*NT];
__device__ float g_gW1T[RR*CT];
__device__ float g_tW1T[RR*NCO];
__device__ float g_w1T[2*CC*CC];          // conv1 [tap][c][o]
__device__ float g_w2T[2*CC*CC];          // conv2 [tap][c][o]
__device__ float g_rT[CC*CC];             // res_w [c][o]

// ------------------------- f32x2 helpers -----------------------------------
__device__ __forceinline__ unsigned long long dup2(float v) {
    unsigned long long r; unsigned u = __float_as_uint(v);
    asm("mov.b64 %0, {%1, %1};" : "=l"(r) : "r"(u));
    return r;
}
__device__ __forceinline__ void fma2(unsigned long long& d,
                                     unsigned long long a, unsigned long long b) {
    asm("fma.rn.f32x2 %0, %1, %2, %0;" : "+l"(d) : "l"(a), "l"(b));
}
__device__ __forceinline__ float lo32(unsigned long long v) {
    return __uint_as_float((unsigned)v);
}
__device__ __forceinline__ float hi32(unsigned long long v) {
    return __uint_as_float((unsigned)(v >> 32));
}

// ------------------------- K0: weight prep (transposes) --------------------
__global__ void k_prep(const float* __restrict__ a0W1, const float* __restrict__ gW1,
                       const float* __restrict__ tW1, const float* __restrict__ c1w,
                       const float* __restrict__ c2w, const float* __restrict__ rw) {
    int e = blockIdx.x * 256 + threadIdx.x;
    if (e < NT*RR)  { int k = e/RR, r = e - k*RR; g_a0W1T[r*NT + k] = a0W1[e]; return; }
    e -= NT*RR;
    if (e < CT*RR)  { int k = e/RR, r = e - k*RR; g_gW1T[r*CT + k] = gW1[e]; return; }
    e -= CT*RR;
    if (e < NCO*RR) { int k = e/RR, r = e - k*RR; g_tW1T[r*NCO + k] = tW1[e]; return; }
    e -= NCO*RR;
    if (e < CC*CC) {
        int o = e >> 6, c = e & 63;
        g_w1T[c*CC + o]         = c1w[e*2 + 0];
        g_w1T[CC*CC + c*CC + o] = c1w[e*2 + 1];
        g_w2T[c*CC + o]         = c2w[e*2 + 0];
        g_w2T[CC*CC + c*CC + o] = c2w[e*2 + 1];
        g_rT[c*CC + o]          = rw[e];
    }
}

// ------------------------- K1: channel-attn projections --------------------
__global__ void k_attA_proj(const float* __restrict__ x, const float* __restrict__ W2) {
    int bc = blockIdx.x;                       // b*64 + c
    const float* xf = x + (size_t)bc * NT;
    float a1[RR], a2[RR];
#pragma unroll
    for (int r = 0; r < RR; r++) { a1[r] = 0.f; a2[r] = 0.f; }
    for (int k = threadIdx.x; k < NT; k += 256) {
        float xv = xf[k];
#pragma unroll
        for (int r = 0; r < RR; r++) {
            a1[r] += xv * g_a0W1T[r*NT + k];
            a2[r] += xv * W2[r*NT + k];
        }
    }
    __shared__ float red[8][2*RR];
    int lane = threadIdx.x & 31, warp = threadIdx.x >> 5;
#pragma unroll
    for (int r = 0; r < RR; r++) {
#pragma unroll
        for (int off = 16; off > 0; off >>= 1) {
            a1[r] += __shfl_down_sync(0xffffffffu, a1[r], off);
            a2[r] += __shfl_down_sync(0xffffffffu, a2[r], off);
        }
    }
    if (lane == 0) {
#pragma unroll
        for (int r = 0; r < RR; r++) { red[warp][r] = a1[r]; red[warp][RR+r] = a2[r]; }
    }
    __syncthreads();
    if (threadIdx.x < 2*RR) {
        float s = 0.f;
#pragma unroll
        for (int w = 0; w < 8; w++) s += red[w][threadIdx.x];
        int b = bc >> 6, c = bc & 63;
        if (threadIdx.x < RR) g_s1a[(b*CC + c)*RR + threadIdx.x] = s;
        else                  g_s2a[(b*RR + (threadIdx.x - RR))*CC + c] = s;
    }
}

// ------------------------- K2: channel-attn softmax (64x64) ----------------
__global__ void k_attA_soft() {
    int b = blockIdx.x >> 6, i = blockIdx.x & 63;
    int j = threadIdx.x;                       // 64 threads
    float s = 0.f;
#pragma unroll
    for (int r = 0; r < RR; r++) s += g_s1a[(b*CC + i)*RR + r] * g_s2a[(b*RR + r)*CC + j];
    s *= rsqrtf((float)NT);
    __shared__ float sm[CC];
    sm[j] = s; __syncthreads();
    float mx = -1e30f;
    for (int jj = 0; jj < CC; jj++) mx = fmaxf(mx, sm[jj]);
    float e = expf(s - mx);
    __syncthreads();
    sm[j] = e; __syncthreads();
    float sum = 0.f;
    for (int jj = 0; jj < CC; jj++) sum += sm[jj];
    g_att0[(b*CC + i)*CC + j] = e / sum;
}

// ------------------------- K3: x1 = att0 @ xf -------------------------------
__global__ void k_chan_apply(const float* __restrict__ x) {
    int b = blockIdx.y;
    int k0 = blockIdx.x * 64;
    __shared__ float attsT[CC][68];            // [j][c], padded
    __shared__ float xfs[CC][64];              // [j][kk]
    int tid = threadIdx.x;                     // 256
    for (int e = tid; e < CC*CC; e += 256) {
        int c = e >> 6, j = e & 63;
        attsT[j][c] = g_att0[b*CC*CC + e];
    }
    for (int e = tid; e < CC*64; e += 256) {
        int j = e >> 6, kk = e & 63;
        xfs[j][kk] = x[(size_t)(b*CC + j)*NT + k0 + kk];
    }
    __syncthreads();
    int kk = tid & 63, cg = tid >> 6;          // cg: 0..3 -> 16 c's each
    float4 acc[4];
#pragma unroll
    for (int q = 0; q < 4; q++) acc[q] = make_float4(0.f, 0.f, 0.f, 0.f);
    for (int j = 0; j < CC; j++) {
        float xv = xfs[j][kk];
        const float4* ap = (const float4*)&attsT[j][cg*16];
#pragma unroll
        for (int q = 0; q < 4; q++) {
            float4 a = ap[q];
            acc[q].x += a.x * xv; acc[q].y += a.y * xv;
            acc[q].z += a.z * xv; acc[q].w += a.w * xv;
        }
    }
#pragma unroll
    for (int q = 0; q < 4; q++) {
        int c = cg*16 + q*4;
        g_x1[(size_t)(b*CC + c + 0)*NT + k0 + kk] = acc[q].x;
        g_x1[(size_t)(b*CC + c + 1)*NT + k0 + kk] = acc[q].y;
        g_x1[(size_t)(b*CC + c + 2)*NT + k0 + kk] = acc[q].z;
        g_x1[(size_t)(b*CC + c + 3)*NT + k0 + kk] = acc[q].w;
    }
}

// ------------------------- K4: graph-attn projections ----------------------
__global__ void k_gatt_proj(const float* __restrict__ W2) {
    int bn = blockIdx.x;
    int b = bn / NN, n = bn - b*NN;
    float a1[RR], a2[RR];
#pragma unroll
    for (int r = 0; r < RR; r++) { a1[r] = 0.f; a2[r] = 0.f; }
    for (int idx = threadIdx.x; idx < CT; idx += 256) {
        int c = idx / TT, t = idx - c*TT;
        float xv = g_x1[(size_t)((b*CC + c)*NN + n)*TT + t];
#pragma unroll
        for (int r = 0; r < RR; r++) {
            a1[r] += xv * g_gW1T[r*CT + idx];
            a2[r] += xv * W2[r*CT + idx];
        }
    }
    __shared__ float red[8][2*RR];
    int lane = threadIdx.x & 31, warp = threadIdx.x >> 5;
#pragma unroll
    for (int r = 0; r < RR; r++) {
#pragma unroll
        for (int off = 16; off > 0; off >>= 1) {
            a1[r] += __shfl_down_sync(0xffffffffu, a1[r], off);
            a2[r] += __shfl_down_sync(0xffffffffu, a2[r], off);
        }
    }
    if (lane == 0) {
#pragma unroll
        for (int r = 0; r < RR; r++) { red[warp][r] = a1[r]; red[warp][RR+r] = a2[r]; }
    }
    __syncthreads();
    if (threadIdx.x < 2*RR) {
        float s = 0.f;
#pragma unroll
        for (int w = 0; w < 8; w++) s += red[w][threadIdx.x];
        if (threadIdx.x < RR) g_s1g[(b*NN + n)*RR + threadIdx.x] = s;
        else                  g_s2g[(b*RR + (threadIdx.x - RR))*NN + n] = s;
    }
}

// ------------------------- K5: graph softmax * A_adj -----------------------
__global__ void k_gatt_soft(const float* __restrict__ A_adj) {
    int bi = blockIdx.x;
    int b = bi / NN, i = bi - b*NN;
    __shared__ float sc[NN];
    __shared__ float s1r[RR];
    __shared__ float red[256];
    int tid = threadIdx.x;
    if (tid < RR) s1r[tid] = g_s1g[(size_t)(b*NN + i)*RR + tid];
    __syncthreads();
    float lmax = -1e30f;
    float scale = rsqrtf((float)CT);
    for (int j = tid; j < NN; j += 256) {
        float s = 0.f;
#pragma unroll
        for (int r = 0; r < RR; r++) s += s1r[r] * g_s2g[(size_t)(b*RR + r)*NN + j];
        s *= scale;
        sc[j] = s;
        lmax = fmaxf(lmax, s);
    }
    red[tid] = lmax; __syncthreads();
    for (int off = 128; off > 0; off >>= 1) {
        if (tid < off) red[tid] = fmaxf(red[tid], red[tid + off]);
        __syncthreads();
    }
    float mx = red[0];
    __syncthreads();
    float lsum = 0.f;
    for (int j = tid; j < NN; j += 256) {
        float e = expf(sc[j] - mx);
        sc[j] = e;
        lsum += e;
    }
    red[tid] = lsum; __syncthreads();
    for (int off = 128; off > 0; off >>= 1) {
        if (tid < off) red[tid] += red[tid + off];
        __syncthreads();
    }
    float inv = 1.f / red[0];
    for (int j = tid; j < NN; j += 256) {
        g_Ag[((size_t)b*NN + i)*NN + j] = sc[j] * inv * A_adj[i*NN + j];
    }
}

// ------------------------- K6: y = x1 . gcn_W  (per (b,m) tile) ------------
__global__ void k_gcnmix(const float* __restrict__ gcn_W) {
    int bm = blockIdx.x;
    int b = bm / NN, m = bm - b*NN;
    __shared__ float xs[CC*TT];
    __shared__ float Ws[CC*CC];
    int tid = threadIdx.x;                     // 384
    for (int e = tid; e < CC*TT; e += 384) {
        int c = e / TT, t = e - c*TT;
        xs[e] = g_x1[(size_t)((b*CC + c)*NN + m)*TT + t];
    }
    for (int e = tid; e < CC*CC; e += 384) Ws[e] = gcn_W[e];
    __syncthreads();
    int og = tid / TT, t = tid - og*TT, o4 = og*4;
    float4 acc = make_float4(0.f, 0.f, 0.f, 0.f);
#pragma unroll 8
    for (int c = 0; c < CC; c++) {
        float xv = xs[c*TT + t];
        float4 w = *(const float4*)&Ws[c*CC + o4];
        acc.x += w.x * xv; acc.y += w.y * xv; acc.z += w.z * xv; acc.w += w.w * xv;
    }
    size_t base = (size_t)bm * CT;
    g_y[base + (o4 + 0)*TT + t] = acc.x;
    g_y[base + (o4 + 1)*TT + t] = acc.y;
    g_y[base + (o4 + 2)*TT + t] = acc.z;
    g_y[base + (o4 + 3)*TT + t] = acc.w;
}

// ------------------------- K7: big GEMM gb = Ag @ y (f32x2) ----------------
// per batch: [1000 x 1000] @ [1000 x 1536]. Tile 128x128, k-tile 16, 8x8 micro.
#define GTM 128
#define GTN 128
#define GTK 16
__global__ void __launch_bounds__(256) k_gemm() {
    int b  = blockIdx.z;
    int n0 = blockIdx.y * GTM;
    int j0 = blockIdx.x * GTN;
    const float* A  = g_Ag + (size_t)b*NN*NN;
    const float* Bm = g_y  + (size_t)b*NN*CT;
    float*       Cm = g_gb + (size_t)b*NN*CT;
    __shared__ float As[GTK][GTM + 4];        // [kk][n], row 528B (16B aligned)
    __shared__ float Bs[GTK][GTN + 4];        // [kk][j]
    int tid = threadIdx.x;                     // 256
    int tx = tid & 15;                         // col group (8 cols)
    int ty = tid >> 4;                         // row group (8 rows)
    int an = tid >> 1, ah = (tid & 1) * 8;     // A load: row an, k-off ah (8 floats)
    int bk = tid >> 4, bj = (tid & 15) * 8;    // B load: k-row bk, col bj (8 floats)
    const float4 z4 = make_float4(0.f, 0.f, 0.f, 0.f);

    unsigned long long acc[8][4];
#pragma unroll
    for (int i = 0; i < 8; i++)
#pragma unroll
        for (int j = 0; j < 4; j++) acc[i][j] = 0ull;

    const int NKT = (NN + GTK - 1) / GTK;      // 63 (63*16=1008)
    for (int kt = 0; kt < NKT; kt++) {
        int k0 = kt * GTK;
        {
            int n = n0 + an;
            bool va = (n < NN) && (k0 + ah < NN);   // NN%8==0 -> 8-float chunk all-valid
            const float* pA = A + (size_t)n*NN + k0 + ah;
            float4 a0 = va ? *(const float4*)pA : z4;
            float4 a1 = va ? *(const float4*)(pA + 4) : z4;
            As[ah + 0][an] = a0.x; As[ah + 1][an] = a0.y;
            As[ah + 2][an] = a0.z; As[ah + 3][an] = a0.w;
            As[ah + 4][an] = a1.x; As[ah + 5][an] = a1.y;
            As[ah + 6][an] = a1.z; As[ah + 7][an] = a1.w;
            bool vb = (k0 + bk < NN);
            const float* pB = Bm + (size_t)(k0 + bk)*CT + j0 + bj;
            *(float4*)&Bs[bk][bj]     = vb ? *(const float4*)pB : z4;
            *(float4*)&Bs[bk][bj + 4] = vb ? *(const float4*)(pB + 4) : z4;
        }
        __syncthreads();
#pragma unroll
        for (int kk = 0; kk < GTK; kk++) {
            float4 a0 = *(const float4*)&As[kk][ty*8];
            float4 a1 = *(const float4*)&As[kk][ty*8 + 4];
            ulonglong2 b0 = *(const ulonglong2*)&Bs[kk][tx*8];
            ulonglong2 b1 = *(const ulonglong2*)&Bs[kk][tx*8 + 4];
            unsigned long long ad[8];
            ad[0] = dup2(a0.x); ad[1] = dup2(a0.y); ad[2] = dup2(a0.z); ad[3] = dup2(a0.w);
            ad[4] = dup2(a1.x); ad[5] = dup2(a1.y); ad[6] = dup2(a1.z); ad[7] = dup2(a1.w);
#pragma unroll
            for (int i = 0; i < 8; i++) {
                fma2(acc[i][0], ad[i], b0.x);
                fma2(acc[i][1], ad[i], b0.y);
                fma2(acc[i][2], ad[i], b1.x);
                fma2(acc[i][3], ad[i], b1.y);
            }
        }
        __syncthreads();
    }
#pragma unroll
    for (int i = 0; i < 8; i++) {
        int n = n0 + ty*8 + i;
        if (n < NN) {
            float* cp = Cm + (size_t)n*CT + j0 + tx*8;
            float4 v0 = make_float4(lo32(acc[i][0]), hi32(acc[i][0]),
                                    lo32(acc[i][1]), hi32(acc[i][1]));
            float4 v1 = make_float4(lo32(acc[i][2]), hi32(acc[i][2]),
                                    lo32(acc[i][3]), hi32(acc[i][3]));
            *(float4*)cp = v0;
            *(float4*)(cp + 4) = v1;
        }
    }
}

// ------------------------- K8: temporal-attn projections -------------------
__global__ void k_tatt_proj(const float* __restrict__ W2) {
    int bt = blockIdx.x;                       // b*24 + t
    int b = bt / TT, t = bt - b*TT;
    float a1[RR], a2[RR];
#pragma unroll
    for (int r = 0; r < RR; r++) { a1[r] = 0.f; a2[r] = 0.f; }
    for (int idx = threadIdx.x; idx < NCO; idx += 256) {
        int n = idx >> 6, o = idx & 63;
        float gv = g_gb[(size_t)(b*NN + n)*CT + o*TT + t];
#pragma unroll
        for (int r = 0; r < RR; r++) {
            a1[r] += gv * g_tW1T[r*NCO + idx];
            a2[r] += gv * W2[r*NCO + idx];
        }
    }
    __shared__ float red[8][2*RR];
    int lane = threadIdx.x & 31, warp = threadIdx.x >> 5;
#pragma unroll
    for (int r = 0; r < RR; r++) {
#pragma unroll
        for (int off = 16; off > 0; off >>= 1) {
            a1[r] += __shfl_down_sync(0xffffffffu, a1[r], off);
            a2[r] += __shfl_down_sync(0xffffffffu, a2[r], off);
        }
    }
    if (lane == 0) {
#pragma unroll
        for (int r = 0; r < RR; r++) { red[warp][r] = a1[r]; red[warp][RR+r] = a2[r]; }
    }
    __syncthreads();
    if (threadIdx.x < 2*RR) {
        float s = 0.f;
#pragma unroll
        for (int w = 0; w < 8; w++) s += red[w][threadIdx.x];
        if (threadIdx.x < RR) g_s1t[(b*TT + t)*RR + threadIdx.x] = s;
        else                  g_s2t[(b*RR + (threadIdx.x - RR))*TT + t] = s;
    }
}

// ------------------------- K9: temporal softmax (24x24) --------------------
__global__ void k_tatt_soft() {
    int b = blockIdx.x;
    int i = threadIdx.x;
    if (i >= TT) return;
    float sc[TT];
    float scale = rsqrtf((float)NCO);
#pragma unroll
    for (int j = 0; j < TT; j++) {
        float s = 0.f;
#pragma unroll
        for (int r = 0; r < RR; r++) s += g_s1t[(b*TT + i)*RR + r] * g_s2t[(b*RR + r)*TT + j];
        sc[j] = s * scale;
    }
    float mx = -1e30f;
#pragma unroll
    for (int j = 0; j < TT; j++) mx = fmaxf(mx, sc[j]);
    float sum = 0.f;
#pragma unroll
    for (int j = 0; j < TT; j++) { sc[j] = expf(sc[j] - mx); sum += sc[j]; }
    float inv = 1.f / sum;
#pragma unroll
    for (int j = 0; j < TT; j++) g_attT[(b*TT + i)*TT + j] = sc[j] * inv;
}

// ------------------------- K10: fused TCN-apply + convs + res + LN ---------
__global__ void k_final(const float* __restrict__ x,
                        const float* __restrict__ c1b,
                        const float* __restrict__ c2b,
                        const float* __restrict__ rb,
                        const float* __restrict__ lng,
                        const float* __restrict__ lnb,
                        float* __restrict__ out) {
    int bn = blockIdx.x;
    int b = bn / NN, n = bn - b*NN;
    __shared__ float gt[CT];
    __shared__ float at[TT*TT];
    __shared__ float xa[CT];
    __shared__ float xb[CT];
    __shared__ float xt[CT];
    __shared__ float ps[TT][16];
    __shared__ float pq[TT][16];
    __shared__ float mus[TT], rsg[TT];
    int tid = threadIdx.x;                     // 384
    for (int e = tid; e < CT; e += 384) gt[e] = g_gb[(size_t)bn*CT + e];
    for (int e = tid; e < TT*TT; e += 384) at[e] = g_attT[b*TT*TT + e];
    for (int e = tid; e < CT; e += 384) {
        int c = e / TT, t = e - c*TT;
        xt[e] = x[(size_t)((b*CC + c)*NN + n)*TT + t];
    }
    __syncthreads();
    int og = tid / TT, t = tid - og*TT, o4 = og*4;

    // temporal attention apply
    float4 a4 = make_float4(0.f, 0.f, 0.f, 0.f);
#pragma unroll
    for (int tp = 0; tp < TT; tp++) {
        float av = at[t*TT + tp];
        a4.x += av * gt[(o4 + 0)*TT + tp];
        a4.y += av * gt[(o4 + 1)*TT + tp];
        a4.z += av * gt[(o4 + 2)*TT + tp];
        a4.w += av * gt[(o4 + 3)*TT + tp];
    }
    xa[(o4 + 0)*TT + t] = a4.x;
    xa[(o4 + 1)*TT + t] = a4.y;
    xa[(o4 + 2)*TT + t] = a4.z;
    xa[(o4 + 3)*TT + t] = a4.w;
    __syncthreads();

    // conv1, dilation 1
    {
        float4 acc = __ldg((const float4*)(c1b + o4));
#pragma unroll 8
        for (int c = 0; c < CC; c++) {
            float x0 = (t >= 1) ? xa[c*TT + t - 1] : 0.f;
            float x1v = xa[c*TT + t];
            float4 w0 = __ldg((const float4*)(g_w1T + c*CC + o4));
            float4 w1 = __ldg((const float4*)(g_w1T + CC*CC + c*CC + o4));
            acc.x += w0.x*x0 + w1.x*x1v;
            acc.y += w0.y*x0 + w1.y*x1v;
            acc.z += w0.z*x0 + w1.z*x1v;
            acc.w += w0.w*x0 + w1.w*x1v;
        }
        xb[(o4 + 0)*TT + t] = fmaxf(acc.x, 0.f);
        xb[(o4 + 1)*TT + t] = fmaxf(acc.y, 0.f);
        xb[(o4 + 2)*TT + t] = fmaxf(acc.z, 0.f);
        xb[(o4 + 3)*TT + t] = fmaxf(acc.w, 0.f);
    }
    __syncthreads();

    // conv2, dilation 2
    float v[4];
    {
        float4 acc = __ldg((const float4*)(c2b + o4));
#pragma unroll 8
        for (int c = 0; c < CC; c++) {
            float x0 = (t >= 2) ? xb[c*TT + t - 2] : 0.f;
            float x1v = xb[c*TT + t];
            float4 w0 = __ldg((const float4*)(g_w2T + c*CC + o4));
            float4 w1 = __ldg((const float4*)(g_w2T + CC*CC + c*CC + o4));
            acc.x += w0.x*x0 + w1.x*x1v;
            acc.y += w0.y*x0 + w1.y*x1v;
            acc.z += w0.z*x0 + w1.z*x1v;
            acc.w += w0.w*x0 + w1.w*x1v;
        }
        v[0] = fmaxf(acc.x, 0.f);
        v[1] = fmaxf(acc.y, 0.f);
        v[2] = fmaxf(acc.z, 0.f);
        v[3] = fmaxf(acc.w, 0.f);
    }

    // residual + relu
    {
        float4 acc = __ldg((const float4*)(rb + o4));
#pragma unroll 8
        for (int c = 0; c < CC; c++) {
            float xv = xt[c*TT + t];
            float4 rw = __ldg((const float4*)(g_rT + c*CC + o4));
            acc.x += rw.x*xv; acc.y += rw.y*xv; acc.z += rw.z*xv; acc.w += rw.w*xv;
        }
        v[0] = fmaxf(v[0] + acc.x, 0.f);
        v[1] = fmaxf(v[1] + acc.y, 0.f);
        v[2] = fmaxf(v[2] + acc.z, 0.f);
        v[3] = fmaxf(v[3] + acc.w, 0.f);
    }

    // LayerNorm over channel
    float s = v[0] + v[1] + v[2] + v[3];
    float q = v[0]*v[0] + v[1]*v[1] + v[2]*v[2] + v[3]*v[3];
    ps[t][og] = s; pq[t][og] = q;
    __syncthreads();
    if (tid < TT) {
        float S = 0.f, Q = 0.f;
#pragma unroll
        for (int g2 = 0; g2 < 16; g2++) { S += ps[tid][g2]; Q += pq[tid][g2]; }
        float mu = S * (1.f/CC);
        float var = Q * (1.f/CC) - mu*mu;
        mus[tid] = mu;
        rsg[tid] = rsqrtf(var + 1e-5f);
    }
    __syncthreads();
    float mu = mus[t], rs = rsg[t];
#pragma unroll
    for (int i = 0; i < 4; i++) {
        int o = o4 + i;
        out[(size_t)((b*CC + o)*NN + n)*TT + t] =
            (v[i] - mu) * rs * __ldg(lng + o) + __ldg(lnb + o);
    }
}

// ------------------------- launch ------------------------------------------
extern "C" void kernel_launch(void* const* d_in, const int* in_sizes, int n_in,
                              void* d_out, int out_size) {
    const float* x     = (const float*)d_in[0];
    const float* A_adj = (const float*)d_in[1];
    const float* a0W1  = (const float*)d_in[2];
    const float* a0W2  = (const float*)d_in[3];
    const float* gW1   = (const float*)d_in[4];
    const float* gW2   = (const float*)d_in[5];
    const float* gcnW  = (const float*)d_in[6];
    const float* tW1   = (const float*)d_in[7];
    const float* tW2   = (const float*)d_in[8];
    const float* c1w   = (const float*)d_in[9];
    const float* c1b   = (const float*)d_in[10];
    const float* c2w   = (const float*)d_in[11];
    const float* c2b   = (const float*)d_in[12];
    const float* resw  = (const float*)d_in[13];
    const float* resb  = (const float*)d_in[14];
    const float* lng   = (const float*)d_in[15];
    const float* lnb   = (const float*)d_in[16];
    float* out = (float*)d_out;

    k_prep<<<3514, 256>>>(a0W1, gW1, tW1, c1w, c2w, resw);
    k_attA_proj<<<BB*CC, 256>>>(x, a0W2);
    k_attA_soft<<<BB*CC, CC>>>();
    k_chan_apply<<<dim3(NT/64, BB), 256>>>(x);
    k_gatt_proj<<<BB*NN, 256>>>(gW2);
    k_gatt_soft<<<BB*NN, 256>>>(A_adj);
    k_gcnmix<<<BB*NN, 384>>>(gcnW);
    k_gemm<<<dim3(CT/GTN, (NN + GTM - 1)/GTM, BB), 256>>>();
    k_tatt_proj<<<BB*TT, 256>>>(tW2);
    k_tatt_soft<<<BB, 32>>>();
    k_final<<<BB*NN, 384>>>(x, c1b, c2b, resb, lng, lnb, out);
}

// round 5
// speedup vs baseline: 2.2215x; 1.4863x over previous
#include <cuda_runtime.h>
#include <math.h>

#define BB 8
#define CC 64
#define NN 1000
#define TT 24
#define RR 10
#define NT 24000     // NN*TT
#define CT 1536      // CC*TT
#define NCO 64000    // NN*CC

// ------------------------- scratch (device globals, no allocs) -------------
__device__ float g_x1[BB*CC*NT];          // x1 [b,c,n,t]
__device__ float g_s1a[BB*CC*RR];
__device__ float g_s2a[BB*RR*CC];
__device__ float g_att0[BB*CC*CC];
__device__ float g_s1g[BB*NN*RR];
__device__ float g_s2g[BB*RR*NN];
__device__ float g_Ag[BB*NN*NN];          // gated adjacency [b,n,m]
__device__ float g_y[BB*NN*CT];           // (x1 . gcn_W)  [b,m,(o*T+t)]
__device__ float g_gb[BB*NN*CT];          // g             [b,n,(o*T+t)]
__device__ float g_s1t[BB*TT*RR];
__device__ float g_s2t[BB*RR*TT];
__device__ float g_attT[BB*TT*TT];
// transposed weights
__device__ float g_a0W1T[RR*NT];
__device__ float g_gW1T[RR*CT];
__device__ float g_tW1T[RR*NCO];
__device__ float g_w1T[2*CC*CC];          // conv1 [tap][c][o]
__device__ float g_w2T[2*CC*CC];          // conv2 [tap][c][o]
__device__ float g_rT[CC*CC];             // res_w [c][o]

// ------------------------- f32x2 helpers -----------------------------------
__device__ __forceinline__ unsigned long long dup2(float v) {
    unsigned long long r; unsigned u = __float_as_uint(v);
    asm("mov.b64 %0, {%1, %1};" : "=l"(r) : "r"(u));
    return r;
}
__device__ __forceinline__ unsigned long long pack2(float lo, float hi) {
    unsigned long long r;
    asm("mov.b64 %0, {%1, %2};" : "=l"(r) : "r"(__float_as_uint(lo)), "r"(__float_as_uint(hi)));
    return r;
}
__device__ __forceinline__ void fma2(unsigned long long& d,
                                     unsigned long long a, unsigned long long b) {
    asm("fma.rn.f32x2 %0, %1, %2, %0;" : "+l"(d) : "l"(a), "l"(b));
}
__device__ __forceinline__ float lo32(unsigned long long v) {
    return __uint_as_float((unsigned)v);
}
__device__ __forceinline__ float hi32(unsigned long long v) {
    return __uint_as_float((unsigned)(v >> 32));
}

// ------------------------- K0: weight prep (transposes) --------------------
__global__ void k_prep(const float* __restrict__ a0W1, const float* __restrict__ gW1,
                       const float* __restrict__ tW1, const float* __restrict__ c1w,
                       const float* __restrict__ c2w, const float* __restrict__ rw) {
    int e = blockIdx.x * 256 + threadIdx.x;
    if (e < NT*RR)  { int k = e/RR, r = e - k*RR; g_a0W1T[r*NT + k] = a0W1[e]; return; }
    e -= NT*RR;
    if (e < CT*RR)  { int k = e/RR, r = e - k*RR; g_gW1T[r*CT + k] = gW1[e]; return; }
    e -= CT*RR;
    if (e < NCO*RR) { int k = e/RR, r = e - k*RR; g_tW1T[r*NCO + k] = tW1[e]; return; }
    e -= NCO*RR;
    if (e < CC*CC) {
        int o = e >> 6, c = e & 63;
        g_w1T[c*CC + o]         = c1w[e*2 + 0];
        g_w1T[CC*CC + c*CC + o] = c1w[e*2 + 1];
        g_w2T[c*CC + o]         = c2w[e*2 + 0];
        g_w2T[CC*CC + c*CC + o] = c2w[e*2 + 1];
        g_rT[c*CC + o]          = rw[e];
    }
}

// ------------------------- K1: channel-attn projections (float4) -----------
__global__ void k_attA_proj(const float* __restrict__ x, const float* __restrict__ W2) {
    int bc = blockIdx.x;                       // b*64 + c
    const float* xf = x + (size_t)bc * NT;
    float a1[RR], a2[RR];
#pragma unroll
    for (int r = 0; r < RR; r++) { a1[r] = 0.f; a2[r] = 0.f; }
    for (int k4 = threadIdx.x * 4; k4 < NT; k4 += 1024) {
        float4 xv = *(const float4*)(xf + k4);
#pragma unroll
        for (int r = 0; r < RR; r++) {
            float4 w1 = *(const float4*)(g_a0W1T + r*NT + k4);
            float4 w2 = *(const float4*)(W2 + r*NT + k4);
            a1[r] += xv.x*w1.x + xv.y*w1.y + xv.z*w1.z + xv.w*w1.w;
            a2[r] += xv.x*w2.x + xv.y*w2.y + xv.z*w2.z + xv.w*w2.w;
        }
    }
    __shared__ float red[8][2*RR];
    int lane = threadIdx.x & 31, warp = threadIdx.x >> 5;
#pragma unroll
    for (int r = 0; r < RR; r++) {
#pragma unroll
        for (int off = 16; off > 0; off >>= 1) {
            a1[r] += __shfl_down_sync(0xffffffffu, a1[r], off);
            a2[r] += __shfl_down_sync(0xffffffffu, a2[r], off);
        }
    }
    if (lane == 0) {
#pragma unroll
        for (int r = 0; r < RR; r++) { red[warp][r] = a1[r]; red[warp][RR+r] = a2[r]; }
    }
    __syncthreads();
    if (threadIdx.x < 2*RR) {
        float s = 0.f;
#pragma unroll
        for (int w = 0; w < 8; w++) s += red[w][threadIdx.x];
        int b = bc >> 6, c = bc & 63;
        if (threadIdx.x < RR) g_s1a[(b*CC + c)*RR + threadIdx.x] = s;
        else                  g_s2a[(b*RR + (threadIdx.x - RR))*CC + c] = s;
    }
}

// ------------------------- K2: channel-attn softmax (64x64) ----------------
__global__ void k_attA_soft() {
    int b = blockIdx.x >> 6, i = blockIdx.x & 63;
    int j = threadIdx.x;                       // 64 threads
    float s = 0.f;
#pragma unroll
    for (int r = 0; r < RR; r++) s += g_s1a[(b*CC + i)*RR + r] * g_s2a[(b*RR + r)*CC + j];
    s *= rsqrtf((float)NT);
    __shared__ float sm[CC];
    sm[j] = s; __syncthreads();
    float mx = -1e30f;
    for (int jj = 0; jj < CC; jj++) mx = fmaxf(mx, sm[jj]);
    float e = expf(s - mx);
    __syncthreads();
    sm[j] = e; __syncthreads();
    float sum = 0.f;
    for (int jj = 0; jj < CC; jj++) sum += sm[jj];
    g_att0[(b*CC + i)*CC + j] = e / sum;
}

// ------------------------- K3: x1 = att0 @ xf (f32x2, 4x4 micro) -----------
__global__ void __launch_bounds__(256) k_chan_apply(const float* __restrict__ x) {
    int b = blockIdx.y;
    int k0 = blockIdx.x * 64;
    __shared__ float atts[CC][68];             // [j][c], pitch 68 (16B aligned)
    __shared__ float xfs[CC][64];              // [j][kk]
    int tid = threadIdx.x;                     // 256
    for (int e = tid; e < CC*CC; e += 256) {
        int c = e >> 6, j = e & 63;
        atts[j][c] = g_att0[b*CC*CC + e];
    }
    for (int e = tid; e < CC*64; e += 256) {
        int j = e >> 6, kk = e & 63;
        xfs[j][kk] = x[(size_t)(b*CC + j)*NT + k0 + kk];
    }
    __syncthreads();
    int tx = tid & 15, ty = tid >> 4;          // 4 kk x 4 c per thread
    unsigned long long acc[4][2];
#pragma unroll
    for (int i = 0; i < 4; i++) { acc[i][0] = 0ull; acc[i][1] = 0ull; }
#pragma unroll 4
    for (int j = 0; j < CC; j++) {
        float4 a = *(const float4*)&atts[j][ty*4];
        ulonglong2 xv = *(const ulonglong2*)&xfs[j][tx*4];
        unsigned long long d0 = dup2(a.x), d1 = dup2(a.y), d2 = dup2(a.z), d3 = dup2(a.w);
        fma2(acc[0][0], d0, xv.x); fma2(acc[0][1], d0, xv.y);
        fma2(acc[1][0], d1, xv.x); fma2(acc[1][1], d1, xv.y);
        fma2(acc[2][0], d2, xv.x); fma2(acc[2][1], d2, xv.y);
        fma2(acc[3][0], d3, xv.x); fma2(acc[3][1], d3, xv.y);
    }
#pragma unroll
    for (int ci = 0; ci < 4; ci++) {
        int c = ty*4 + ci;
        float4 v = make_float4(lo32(acc[ci][0]), hi32(acc[ci][0]),
                               lo32(acc[ci][1]), hi32(acc[ci][1]));
        *(float4*)&g_x1[(size_t)(b*CC + c)*NT + k0 + tx*4] = v;
    }
}

// ------------------------- K4: graph-attn projections (float4) -------------
__global__ void k_gatt_proj(const float* __restrict__ W2) {
    int bn = blockIdx.x;
    int b = bn / NN, n = bn - b*NN;
    float a1[RR], a2[RR];
#pragma unroll
    for (int r = 0; r < RR; r++) { a1[r] = 0.f; a2[r] = 0.f; }
    for (int k4 = threadIdx.x * 4; k4 < CT; k4 += 1024) {
        int c = k4 / TT, tloc = k4 - c*TT;     // 4-chunks never cross a c row
        float4 xv = *(const float4*)(g_x1 + (size_t)((b*CC + c)*NN + n)*TT + tloc);
#pragma unroll
        for (int r = 0; r < RR; r++) {
            float4 w1 = *(const float4*)(g_gW1T + r*CT + k4);
            float4 w2 = *(const float4*)(W2 + r*CT + k4);
            a1[r] += xv.x*w1.x + xv.y*w1.y + xv.z*w1.z + xv.w*w1.w;
            a2[r] += xv.x*w2.x + xv.y*w2.y + xv.z*w2.z + xv.w*w2.w;
        }
    }
    __shared__ float red[8][2*RR];
    int lane = threadIdx.x & 31, warp = threadIdx.x >> 5;
#pragma unroll
    for (int r = 0; r < RR; r++) {
#pragma unroll
        for (int off = 16; off > 0; off >>= 1) {
            a1[r] += __shfl_down_sync(0xffffffffu, a1[r], off);
            a2[r] += __shfl_down_sync(0xffffffffu, a2[r], off);
        }
    }
    if (lane == 0) {
#pragma unroll
        for (int r = 0; r < RR; r++) { red[warp][r] = a1[r]; red[warp][RR+r] = a2[r]; }
    }
    __syncthreads();
    if (threadIdx.x < 2*RR) {
        float s = 0.f;
#pragma unroll
        for (int w = 0; w < 8; w++) s += red[w][threadIdx.x];
        if (threadIdx.x < RR) g_s1g[(b*NN + n)*RR + threadIdx.x] = s;
        else                  g_s2g[(b*RR + (threadIdx.x - RR))*NN + n] = s;
    }
}

// ------------------------- K5: graph softmax * A_adj -----------------------
__global__ void k_gatt_soft(const float* __restrict__ A_adj) {
    int bi = blockIdx.x;
    int b = bi / NN, i = bi - b*NN;
    __shared__ float sc[NN];
    __shared__ float s1r[RR];
    __shared__ float red[256];
    int tid = threadIdx.x;
    if (tid < RR) s1r[tid] = g_s1g[(size_t)(b*NN + i)*RR + tid];
    __syncthreads();
    float lmax = -1e30f;
    float scale = rsqrtf((float)CT);
    for (int j = tid; j < NN; j += 256) {
        float s = 0.f;
#pragma unroll
        for (int r = 0; r < RR; r++) s += s1r[r] * g_s2g[(size_t)(b*RR + r)*NN + j];
        s *= scale;
        sc[j] = s;
        lmax = fmaxf(lmax, s);
    }
    red[tid] = lmax; __syncthreads();
    for (int off = 128; off > 0; off >>= 1) {
        if (tid < off) red[tid] = fmaxf(red[tid], red[tid + off]);
        __syncthreads();
    }
    float mx = red[0];
    __syncthreads();
    float lsum = 0.f;
    for (int j = tid; j < NN; j += 256) {
        float e = expf(sc[j] - mx);
        sc[j] = e;
        lsum += e;
    }
    red[tid] = lsum; __syncthreads();
    for (int off = 128; off > 0; off >>= 1) {
        if (tid < off) red[tid] += red[tid + off];
        __syncthreads();
    }
    float inv = 1.f / red[0];
    for (int j = tid; j < NN; j += 256) {
        g_Ag[((size_t)b*NN + i)*NN + j] = sc[j] * inv * A_adj[i*NN + j];
    }
}

// ------------------------- K6: y = x1 . gcn_W  (per (b,m) tile) ------------
__global__ void k_gcnmix(const float* __restrict__ gcn_W) {
    int bm = blockIdx.x;
    int b = bm / NN, m = bm - b*NN;
    __shared__ float xs[CC*TT];
    __shared__ float Ws[CC*CC];
    int tid = threadIdx.x;                     // 384
    for (int e = tid; e < CC*TT; e += 384) {
        int c = e / TT, t = e - c*TT;
        xs[e] = g_x1[(size_t)((b*CC + c)*NN + m)*TT + t];
    }
    for (int e = tid; e < CC*CC; e += 384) Ws[e] = gcn_W[e];
    __syncthreads();
    int og = tid / TT, t = tid - og*TT, o4 = og*4;
    float4 acc = make_float4(0.f, 0.f, 0.f, 0.f);
#pragma unroll 8
    for (int c = 0; c < CC; c++) {
        float xv = xs[c*TT + t];
        float4 w = *(const float4*)&Ws[c*CC + o4];
        acc.x += w.x * xv; acc.y += w.y * xv; acc.z += w.z * xv; acc.w += w.w * xv;
    }
    size_t base = (size_t)bm * CT;
    g_y[base + (o4 + 0)*TT + t] = acc.x;
    g_y[base + (o4 + 1)*TT + t] = acc.y;
    g_y[base + (o4 + 2)*TT + t] = acc.z;
    g_y[base + (o4 + 3)*TT + t] = acc.w;
}

// ------------------------- K7: big GEMM gb = Ag @ y (f32x2) ----------------
#define GTM 128
#define GTN 128
#define GTK 16
__global__ void __launch_bounds__(256) k_gemm() {
    int b  = blockIdx.z;
    int n0 = blockIdx.y * GTM;
    int j0 = blockIdx.x * GTN;
    const float* A  = g_Ag + (size_t)b*NN*NN;
    const float* Bm = g_y  + (size_t)b*NN*CT;
    float*       Cm = g_gb + (size_t)b*NN*CT;
    __shared__ float As[GTK][GTM + 4];
    __shared__ float Bs[GTK][GTN + 4];
    int tid = threadIdx.x;                     // 256
    int tx = tid & 15;
    int ty = tid >> 4;
    int an = tid >> 1, ah = (tid & 1) * 8;
    int bk = tid >> 4, bj = (tid & 15) * 8;
    const float4 z4 = make_float4(0.f, 0.f, 0.f, 0.f);

    unsigned long long acc[8][4];
#pragma unroll
    for (int i = 0; i < 8; i++)
#pragma unroll
        for (int j = 0; j < 4; j++) acc[i][j] = 0ull;

    const int NKT = (NN + GTK - 1) / GTK;      // 63
    for (int kt = 0; kt < NKT; kt++) {
        int k0 = kt * GTK;
        {
            int n = n0 + an;
            bool va = (n < NN) && (k0 + ah < NN);
            const float* pA = A + (size_t)n*NN + k0 + ah;
            float4 a0 = va ? *(const float4*)pA : z4;
            float4 a1 = va ? *(const float4*)(pA + 4) : z4;
            As[ah + 0][an] = a0.x; As[ah + 1][an] = a0.y;
            As[ah + 2][an] = a0.z; As[ah + 3][an] = a0.w;
            As[ah + 4][an] = a1.x; As[ah + 5][an] = a1.y;
            As[ah + 6][an] = a1.z; As[ah + 7][an] = a1.w;
            bool vb = (k0 + bk < NN);
            const float* pB = Bm + (size_t)(k0 + bk)*CT + j0 + bj;
            *(float4*)&Bs[bk][bj]     = vb ? *(const float4*)pB : z4;
            *(float4*)&Bs[bk][bj + 4] = vb ? *(const float4*)(pB + 4) : z4;
        }
        __syncthreads();
#pragma unroll
        for (int kk = 0; kk < GTK; kk++) {
            float4 a0 = *(const float4*)&As[kk][ty*8];
            float4 a1 = *(const float4*)&As[kk][ty*8 + 4];
            ulonglong2 b0 = *(const ulonglong2*)&Bs[kk][tx*8];
            ulonglong2 b1 = *(const ulonglong2*)&Bs[kk][tx*8 + 4];
            unsigned long long ad[8];
            ad[0] = dup2(a0.x); ad[1] = dup2(a0.y); ad[2] = dup2(a0.z); ad[3] = dup2(a0.w);
            ad[4] = dup2(a1.x); ad[5] = dup2(a1.y); ad[6] = dup2(a1.z); ad[7] = dup2(a1.w);
#pragma unroll
            for (int i = 0; i < 8; i++) {
                fma2(acc[i][0], ad[i], b0.x);
                fma2(acc[i][1], ad[i], b0.y);
                fma2(acc[i][2], ad[i], b1.x);
                fma2(acc[i][3], ad[i], b1.y);
            }
        }
        __syncthreads();
    }
#pragma unroll
    for (int i = 0; i < 8; i++) {
        int n = n0 + ty*8 + i;
        if (n < NN) {
            float* cp = Cm + (size_t)n*CT + j0 + tx*8;
            float4 v0 = make_float4(lo32(acc[i][0]), hi32(acc[i][0]),
                                    lo32(acc[i][1]), hi32(acc[i][1]));
            float4 v1 = make_float4(lo32(acc[i][2]), hi32(acc[i][2]),
                                    lo32(acc[i][3]), hi32(acc[i][3]));
            *(float4*)cp = v0;
            *(float4*)(cp + 4) = v1;
        }
    }
}

// ------------------------- K8: temporal-attn projections (float4 W) --------
__global__ void k_tatt_proj(const float* __restrict__ W2) {
    int bt = blockIdx.x;                       // b*24 + t
    int b = bt / TT, t = bt - b*TT;
    float a1[RR], a2[RR];
#pragma unroll
    for (int r = 0; r < RR; r++) { a1[r] = 0.f; a2[r] = 0.f; }
    for (int i4 = threadIdx.x * 4; i4 < NCO; i4 += 1024) {
        int n = i4 >> 6, o = i4 & 63;          // 4-chunks never cross n
        const float* gp = g_gb + (size_t)(b*NN + n)*CT + o*TT + t;
        float gv0 = gp[0*TT], gv1 = gp[1*TT], gv2 = gp[2*TT], gv3 = gp[3*TT];
#pragma unroll
        for (int r = 0; r < RR; r++) {
            float4 w1 = *(const float4*)(g_tW1T + (size_t)r*NCO + i4);
            float4 w2 = *(const float4*)(W2 + (size_t)r*NCO + i4);
            a1[r] += gv0*w1.x + gv1*w1.y + gv2*w1.z + gv3*w1.w;
            a2[r] += gv0*w2.x + gv1*w2.y + gv2*w2.z + gv3*w2.w;
        }
    }
    __shared__ float red[8][2*RR];
    int lane = threadIdx.x & 31, warp = threadIdx.x >> 5;
#pragma unroll
    for (int r = 0; r < RR; r++) {
#pragma unroll
        for (int off = 16; off > 0; off >>= 1) {
            a1[r] += __shfl_down_sync(0xffffffffu, a1[r], off);
            a2[r] += __shfl_down_sync(0xffffffffu, a2[r], off);
        }
    }
    if (lane == 0) {
#pragma unroll
        for (int r = 0; r < RR; r++) { red[warp][r] = a1[r]; red[warp][RR+r] = a2[r]; }
    }
    __syncthreads();
    if (threadIdx.x < 2*RR) {
        float s = 0.f;
#pragma unroll
        for (int w = 0; w < 8; w++) s += red[w][threadIdx.x];
        if (threadIdx.x < RR) g_s1t[(b*TT + t)*RR + threadIdx.x] = s;
        else                  g_s2t[(b*RR + (threadIdx.x - RR))*TT + t] = s;
    }
}

// ------------------------- K9: temporal softmax (24x24) --------------------
__global__ void k_tatt_soft() {
    int b = blockIdx.x;
    int i = threadIdx.x;
    if (i >= TT) return;
    float sc[TT];
    float scale = rsqrtf((float)NCO);
#pragma unroll
    for (int j = 0; j < TT; j++) {
        float s = 0.f;
#pragma unroll
        for (int r = 0; r < RR; r++) s += g_s1t[(b*TT + i)*RR + r] * g_s2t[(b*RR + r)*TT + j];
        sc[j] = s * scale;
    }
    float mx = -1e30f;
#pragma unroll
    for (int j = 0; j < TT; j++) mx = fmaxf(mx, sc[j]);
    float sum = 0.f;
#pragma unroll
    for (int j = 0; j < TT; j++) { sc[j] = expf(sc[j] - mx); sum += sc[j]; }
    float inv = 1.f / sum;
#pragma unroll
    for (int j = 0; j < TT; j++) g_attT[(b*TT + i)*TT + j] = sc[j] * inv;
}

// ------------------------- K10: fused TCN-apply + convs + res + LN ---------
// 256 threads = 4 n-units x 64 o. Each thread owns (n, o), all 24 t in regs.
__global__ void __launch_bounds__(256) k_final(
        const float* __restrict__ x,
        const float* __restrict__ c1b,
        const float* __restrict__ c2b,
        const float* __restrict__ rb,
        const float* __restrict__ lng,
        const float* __restrict__ lnb,
        float* __restrict__ out) {
    __shared__ float smB[4*CT];                // 24 KB exchange buffer
    __shared__ float at_s[TT*TT];
    __shared__ float mu_s[4][TT], rs_s[4][TT];
    int blk = blockIdx.x;                      // 0..1999
    int b = blk / 250;
    int n0 = (blk - b*250) * 4;
    int tid = threadIdx.x;
    int u = tid >> 6, o = tid & 63;
    int n = n0 + u;

    for (int e = tid; e < TT*TT; e += 256) at_s[e] = g_attT[b*TT*TT + e];

    // own g row -> regs
    float gm[TT];
    {
        const float* gp = g_gb + ((size_t)b*NN + n)*CT + o*TT;
#pragma unroll
        for (int k = 0; k < 6; k++) {
            float4 v = *(const float4*)(gp + 4*k);
            gm[4*k+0] = v.x; gm[4*k+1] = v.y; gm[4*k+2] = v.z; gm[4*k+3] = v.w;
        }
    }
    __syncthreads();

    // ---- stage A: temporal attention, x2[t] = sum_tp at[t][tp]*gm[tp] ----
    float x2[TT];
#pragma unroll
    for (int t = 0; t < TT; t++) x2[t] = 0.f;
#pragma unroll 4
    for (int tp = 0; tp < TT; tp++) {
        float gv = gm[tp];
#pragma unroll
        for (int t = 0; t < TT; t++) x2[t] += at_s[t*TT + tp] * gv;
    }
    {
        float* wp = &smB[u*CT + o*TT];
#pragma unroll
        for (int k = 0; k < 6; k++)
            *(float4*)(wp + 4*k) = make_float4(x2[4*k], x2[4*k+1], x2[4*k+2], x2[4*k+3]);
    }
    __syncthreads();

    // ---- conv1 (d=1), packed f32x2 over t-pairs ----
    unsigned long long yp[12];
    {
        unsigned long long bias = dup2(__ldg(c1b + o));
#pragma unroll
        for (int k = 0; k < 12; k++) yp[k] = bias;
#pragma unroll 4
        for (int c = 0; c < CC; c++) {
            const ulonglong2* xr = (const ulonglong2*)&smB[u*CT + c*TT];
            ulonglong2 p0 = xr[0], p1 = xr[1], p2 = xr[2];
            unsigned long long xp[6] = { p0.x, p0.y, p1.x, p1.y, p2.x, p2.y };
            unsigned long long w0d = dup2(__ldg(g_w1T + c*CC + o));
            unsigned long long w1d = dup2(__ldg(g_w1T + CC*CC + c*CC + o));
            // aligned tap1 on pairs 0..5 (each covers 4 t): xp has 6 u64 = 12 pairs
            // expand to 12 t-pairs:
            unsigned long long tp_[12];
#pragma unroll
            for (int k = 0; k < 6; k++) { tp_[2*k] = xp[k]; }
            // regroup: xp[k] holds t(4k..4k+1)? No: ulonglong = 2 floats.
            // p0.x = t0,t1; p0.y = t2,t3; ... so xp[k] = pair k directly.
            // (fix) pairs:
            tp_[0] = p0.x; tp_[1] = p0.y; tp_[2] = p1.x; tp_[3] = p1.y;
            tp_[4] = p2.x; tp_[5] = p2.y;
            const ulonglong2* xr2 = (const ulonglong2*)&smB[u*CT + c*TT + 8];
            ulonglong2 p3 = xr2[0];        // t8..t11
            (void)p3;
            // Simplest correct: reload all 12 pairs directly
            const unsigned long long* pr = (const unsigned long long*)&smB[u*CT + c*TT];
#pragma unroll
            for (int k = 0; k < 12; k++) tp_[k] = pr[k];
            // tap1 (aligned)
#pragma unroll
            for (int k = 0; k < 12; k++) fma2(yp[k], w1d, tp_[k]);
            // tap0 (shift by one t)
            unsigned long long sh = pack2(0.f, lo32(tp_[0]));
            fma2(yp[0], w0d, sh);
#pragma unroll
            for (int k = 1; k < 12; k++) {
                sh = pack2(hi32(tp_[k-1]), lo32(tp_[k]));
                fma2(yp[k], w0d, sh);
            }
        }
    }
    // relu
    float y1[TT];
#pragma unroll
    for (int k = 0; k < 12; k++) {
        y1[2*k]   = fmaxf(lo32(yp[k]), 0.f);
        y1[2*k+1] = fmaxf(hi32(yp[k]), 0.f);
    }
    __syncthreads();                            // conv1 reads of smB done
    {
        float* wp = &smB[u*CT + o*TT];
#pragma unroll
        for (int k = 0; k < 6; k++)
            *(float4*)(wp + 4*k) = make_float4(y1[4*k], y1[4*k+1], y1[4*k+2], y1[4*k+3]);
    }
    __syncthreads();

    // ---- conv2 (d=2): pair-aligned shift, zero repacks ----
    unsigned long long vp[12];
    {
        unsigned long long bias = dup2(__ldg(c2b + o));
#pragma unroll
        for (int k = 0; k < 12; k++) vp[k] = bias;
#pragma unroll 4
        for (int c = 0; c < CC; c++) {
            const unsigned long long* pr = (const unsigned long long*)&smB[u*CT + c*TT];
            unsigned long long w0d = dup2(__ldg(g_w2T + c*CC + o));
            unsigned long long w1d = dup2(__ldg(g_w2T + CC*CC + c*CC + o));
            unsigned long long prev = 0ull;     // (t=-2,t=-1) = 0
#pragma unroll
            for (int k = 0; k < 12; k++) {
                unsigned long long cur = pr[k];
                fma2(vp[k], w1d, cur);
                fma2(vp[k], w0d, prev);
                prev = cur;
            }
        }
    }
#pragma unroll
    for (int k = 0; k < 12; k++)
        vp[k] = pack2(fmaxf(lo32(vp[k]), 0.f), fmaxf(hi32(vp[k]), 0.f));
    __syncthreads();                            // conv2 reads done

    // load original x into smB (coalesced runs of 24)
    for (int e4 = tid; e4 < CT; e4 += 256) {    // 4*CT/4 = CT float4s
        int f = e4 * 4;
        int u2 = f / CT, rem = f - u2*CT;
        int c = rem / TT, t = rem - c*TT;
        *(float4*)&smB[f] = *(const float4*)(x + (size_t)((b*CC + c)*NN + n0 + u2)*TT + t);
    }
    __syncthreads();

    // ---- residual 1x1 + relu ----
#pragma unroll 4
    for (int c = 0; c < CC; c++) {
        const unsigned long long* pr = (const unsigned long long*)&smB[u*CT + c*TT];
        unsigned long long rwd = dup2(__ldg(g_rT + c*CC + o));
#pragma unroll
        for (int k = 0; k < 12; k++) fma2(vp[k], rwd, pr[k]);
    }
    {
        unsigned long long biasr = dup2(__ldg(rb + o));
        // add bias once (was not included above)
#pragma unroll
        for (int k = 0; k < 12; k++) {
            float lo = fmaxf(lo32(vp[k]) + lo32(biasr), 0.f);
            float hi = fmaxf(hi32(vp[k]) + hi32(biasr), 0.f);
            vp[k] = pack2(lo, hi);
        }
    }
    float v[TT];
#pragma unroll
    for (int k = 0; k < 12; k++) { v[2*k] = lo32(vp[k]); v[2*k+1] = hi32(vp[k]); }
    __syncthreads();                            // residual reads of smB done

    // ---- LayerNorm over o (64) per (u,t) ----
    {
        float* wp = &smB[u*CT + o*TT];
#pragma unroll
        for (int k = 0; k < 6; k++)
            *(float4*)(wp + 4*k) = make_float4(v[4*k], v[4*k+1], v[4*k+2], v[4*k+3]);
    }
    __syncthreads();
    if (tid < 96) {
        int ur = tid / TT, tr = tid - ur*TT;
        float S = 0.f, Q = 0.f;
#pragma unroll 8
        for (int oo = 0; oo < CC; oo++) {
            float val = smB[ur*CT + oo*TT + tr];
            S += val; Q += val*val;
        }
        float mu = S * (1.f/CC);
        float var = Q * (1.f/CC) - mu*mu;
        mu_s[ur][tr] = mu;
        rs_s[ur][tr] = rsqrtf(var + 1e-5f);
    }
    __syncthreads();
    {
        float gmul = __ldg(lng + o), badd = __ldg(lnb + o);
        float* op = out + (size_t)((b*CC + o)*NN + n)*TT;
        float res[TT];
#pragma unroll
        for (int t = 0; t < TT; t++)
            res[t] = (v[t] - mu_s[u][t]) * rs_s[u][t] * gmul + badd;
#pragma unroll
        for (int k = 0; k < 6; k++)
            *(float4*)(op + 4*k) = make_float4(res[4*k], res[4*k+1], res[4*k+2], res[4*k+3]);
    }
}

// ------------------------- launch ------------------------------------------
extern "C" void kernel_launch(void* const* d_in, const int* in_sizes, int n_in,
                              void* d_out, int out_size) {
    const float* x     = (const float*)d_in[0];
    const float* A_adj = (const float*)d_in[1];
    const float* a0W1  = (const float*)d_in[2];
    const float* a0W2  = (const float*)d_in[3];
    const float* gW1   = (const float*)d_in[4];
    const float* gW2   = (const float*)d_in[5];
    const float* gcnW  = (const float*)d_in[6];
    const float* tW1   = (const float*)d_in[7];
    const float* tW2   = (const float*)d_in[8];
    const float* c1w   = (const float*)d_in[9];
    const float* c1b   = (const float*)d_in[10];
    const float* c2w   = (const float*)d_in[11];
    const float* c2b   = (const float*)d_in[12];
    const float* resw  = (const float*)d_in[13];
    const float* resb  = (const float*)d_in[14];
    const float* lng   = (const float*)d_in[15];
    const float* lnb   = (const float*)d_in[16];
    float* out = (float*)d_out;

    k_prep<<<3514, 256>>>(a0W1, gW1, tW1, c1w, c2w, resw);
    k_attA_proj<<<BB*CC, 256>>>(x, a0W2);
    k_attA_soft<<<BB*CC, CC>>>();
    k_chan_apply<<<dim3(NT/64, BB), 256>>>(x);
    k_gatt_proj<<<BB*NN, 256>>>(gW2);
    k_gatt_soft<<<BB*NN, 256>>>(A_adj);
    k_gcnmix<<<BB*NN, 384>>>(gcnW);
    k_gemm<<<dim3(CT/GTN, (NN + GTM - 1)/GTM, BB), 256>>>();
    k_tatt_proj<<<BB*TT, 256>>>(tW2);
    k_tatt_soft<<<BB, 32>>>();
    k_final<<<BB*NN/4, 256>>>(x, c1b, c2b, resb, lng, lnb, out);
}

// round 6
// speedup vs baseline: 2.3492x; 1.0575x over previous
#include <cuda_runtime.h>
#include <math.h>

#define BB 8
#define CC 64
#define NN 1000
#define TT 24
#define RR 10
#define NT 24000     // NN*TT
#define CT 1536      // CC*TT
#define NCO 64000    // NN*CC

// ------------------------- scratch (device globals, no allocs) -------------
__device__ float g_x1t[BB*NN*CT];         // x1 transposed [b][n][(c*T+t)]
__device__ float g_g1[BB*NN*CT];          // Ag @ x1t      [b][n][(c*T+t)]
__device__ float g_s1a[BB*CC*RR];
__device__ float g_s2a[BB*RR*CC];
__device__ float g_att0[BB*CC*CC];
__device__ float g_s1g[BB*NN*RR];
__device__ float g_s2g[BB*RR*NN];
__device__ float g_Ag[BB*NN*NN];          // gated adjacency [b,n,m]
__device__ float g_s1t[BB*TT*RR];
__device__ float g_s2t[BB*RR*TT];
__device__ float g_attT[BB*TT*TT];
// transposed / fused weights
__device__ float g_a0W1T[RR*NT];
__device__ float g_gW1T[RR*CT];
__device__ float g_F1T[RR*NCO];           // fused gcnW . tatt_W1  [r][(n*64+c)]
__device__ float g_F2T[RR*NCO];           // fused gcnW . tatt_W2  [r][(n*64+c)]
__device__ float g_w1T[2*CC*CC];          // conv1 [tap][c][o]
__device__ float g_w2T[2*CC*CC];          // conv2 [tap][c][o]
__device__ float g_rT[CC*CC];             // res_w [c][o]

// ------------------------- f32x2 helpers -----------------------------------
__device__ __forceinline__ unsigned long long dup2(float v) {
    unsigned long long r; unsigned u = __float_as_uint(v);
    asm("mov.b64 %0, {%1, %1};" : "=l"(r) : "r"(u));
    return r;
}
__device__ __forceinline__ unsigned long long pack2(float lo, float hi) {
    unsigned long long r;
    asm("mov.b64 %0, {%1, %2};" : "=l"(r) : "r"(__float_as_uint(lo)), "r"(__float_as_uint(hi)));
    return r;
}
__device__ __forceinline__ void fma2(unsigned long long& d,
                                     unsigned long long a, unsigned long long b) {
    asm("fma.rn.f32x2 %0, %1, %2, %0;" : "+l"(d) : "l"(a), "l"(b));
}
__device__ __forceinline__ float lo32(unsigned long long v) {
    return __uint_as_float((unsigned)v);
}
__device__ __forceinline__ float hi32(unsigned long long v) {
    return __uint_as_float((unsigned)(v >> 32));
}

// ------------------------- K0: weight prep (transposes) --------------------
__global__ void k_prep(const float* __restrict__ a0W1, const float* __restrict__ gW1,
                       const float* __restrict__ c1w, const float* __restrict__ c2w,
                       const float* __restrict__ rw) {
    int e = blockIdx.x * 256 + threadIdx.x;
    if (e < NT*RR)  { int k = e/RR, r = e - k*RR; g_a0W1T[r*NT + k] = a0W1[e]; return; }
    e -= NT*RR;
    if (e < CT*RR)  { int k = e/RR, r = e - k*RR; g_gW1T[r*CT + k] = gW1[e]; return; }
    e -= CT*RR;
    if (e < CC*CC) {
        int o = e >> 6, c = e & 63;
        g_w1T[c*CC + o]         = c1w[e*2 + 0];
        g_w1T[CC*CC + c*CC + o] = c1w[e*2 + 1];
        g_w2T[c*CC + o]         = c2w[e*2 + 0];
        g_w2T[CC*CC + c*CC + o] = c2w[e*2 + 1];
        g_rT[c*CC + o]          = rw[e];
    }
}

// ------------------------- K0b: fuse gcn_W into tatt weights ---------------
// F1T[r][(n,c)] = sum_o gcnW[c,o] * tW1[n*64+o, r]
// F2T[r][(n,c)] = sum_o gcnW[c,o] * tW2[r, n*64+o]
__global__ void k_fuse(const float* __restrict__ gcnW, const float* __restrict__ tW1,
                       const float* __restrict__ tW2) {
    int n = blockIdx.x;
    __shared__ float gs[CC*CC];     // [c][o]
    __shared__ float w1s[CC*RR];    // [o][r]
    __shared__ float w2s[RR*CC];    // [r][o]
    int tid = threadIdx.x;          // 256
    for (int e = tid; e < CC*CC; e += 256) gs[e] = gcnW[e];
    for (int e = tid; e < CC*RR; e += 256) w1s[e] = tW1[(size_t)(n*CC)*RR + e];
    for (int e = tid; e < RR*CC; e += 256) {
        int r = e / CC, o = e - r*CC;
        w2s[e] = tW2[(size_t)r*NCO + n*CC + o];
    }
    __syncthreads();
    for (int idx = tid; idx < CC*RR; idx += 256) {
        int c = idx / RR, r = idx - c*RR;
        float s1 = 0.f, s2 = 0.f;
#pragma unroll 16
        for (int o = 0; o < CC; o++) {
            float g = gs[c*CC + o];
            s1 += g * w1s[o*RR + r];
            s2 += g * w2s[r*CC + o];
        }
        g_F1T[(size_t)r*NCO + n*CC + c] = s1;
        g_F2T[(size_t)r*NCO + n*CC + c] = s2;
    }
}

// ------------------------- K1: channel-attn projections (4 rows/block) -----
__global__ void __launch_bounds__(256) k_attA_proj(const float* __restrict__ x,
                                                   const float* __restrict__ W2) {
    int g0 = blockIdx.x * 4;                   // rows g0..g0+3 (bc index, same b)
    float a1[4][RR], a2[4][RR];
#pragma unroll
    for (int j = 0; j < 4; j++)
#pragma unroll
        for (int r = 0; r < RR; r++) { a1[j][r] = 0.f; a2[j][r] = 0.f; }
    for (int k4 = threadIdx.x * 4; k4 < NT; k4 += 1024) {
        float4 xv[4];
#pragma unroll
        for (int j = 0; j < 4; j++)
            xv[j] = *(const float4*)(x + (size_t)(g0 + j)*NT + k4);
#pragma unroll
        for (int r = 0; r < RR; r++) {
            float4 w1 = *(const float4*)(g_a0W1T + r*NT + k4);
            float4 w2 = *(const float4*)(W2 + r*NT + k4);
#pragma unroll
            for (int j = 0; j < 4; j++) {
                a1[j][r] += xv[j].x*w1.x + xv[j].y*w1.y + xv[j].z*w1.z + xv[j].w*w1.w;
                a2[j][r] += xv[j].x*w2.x + xv[j].y*w2.y + xv[j].z*w2.z + xv[j].w*w2.w;
            }
        }
    }
    __shared__ float red[8][80];
    int lane = threadIdx.x & 31, warp = threadIdx.x >> 5;
#pragma unroll
    for (int j = 0; j < 4; j++)
#pragma unroll
        for (int r = 0; r < RR; r++) {
#pragma unroll
            for (int off = 16; off > 0; off >>= 1) {
                a1[j][r] += __shfl_down_sync(0xffffffffu, a1[j][r], off);
                a2[j][r] += __shfl_down_sync(0xffffffffu, a2[j][r], off);
            }
            if (lane == 0) { red[warp][j*RR + r] = a1[j][r]; red[warp][40 + j*RR + r] = a2[j][r]; }
        }
    __syncthreads();
    int tid = threadIdx.x;
    if (tid < 80) {
        float s = 0.f;
#pragma unroll
        for (int w = 0; w < 8; w++) s += red[w][tid];
        if (tid < 40) {
            int j = tid / RR, r = tid - j*RR;
            g_s1a[(g0 + j)*RR + r] = s;
        } else {
            int k = tid - 40;
            int j = k / RR, r = k - j*RR;
            int bc = g0 + j, b = bc >> 6, c = bc & 63;
            g_s2a[(b*RR + r)*CC + c] = s;
        }
    }
}

// ------------------------- K2: channel-attn softmax (64x64) ----------------
__global__ void k_attA_soft() {
    int b = blockIdx.x >> 6, i = blockIdx.x & 63;
    int j = threadIdx.x;                       // 64 threads
    float s = 0.f;
#pragma unroll
    for (int r = 0; r < RR; r++) s += g_s1a[(b*CC + i)*RR + r] * g_s2a[(b*RR + r)*CC + j];
    s *= rsqrtf((float)NT);
    __shared__ float sm[CC];
    sm[j] = s; __syncthreads();
    float mx = -1e30f;
    for (int jj = 0; jj < CC; jj++) mx = fmaxf(mx, sm[jj]);
    float e = expf(s - mx);
    __syncthreads();
    sm[j] = e; __syncthreads();
    float sum = 0.f;
    for (int jj = 0; jj < CC; jj++) sum += sm[jj];
    g_att0[(b*CC + i)*CC + j] = e / sum;
}

// ------------------------- K3: x1t = att0 @ xf (transposed out) ------------
__global__ void __launch_bounds__(256) k_chan_apply(const float* __restrict__ x) {
    int b = blockIdx.y;
    int k0 = blockIdx.x * 64;
    __shared__ float atts[CC][68];             // [j][c]
    __shared__ float xfs[CC][64];              // [j][kk]
    int tid = threadIdx.x;                     // 256
    for (int e = tid; e < CC*CC; e += 256) {
        int c = e >> 6, j = e & 63;
        atts[j][c] = g_att0[b*CC*CC + e];
    }
    for (int e = tid; e < CC*64; e += 256) {
        int j = e >> 6, kk = e & 63;
        xfs[j][kk] = x[(size_t)(b*CC + j)*NT + k0 + kk];
    }
    __syncthreads();
    int tx = tid & 15, ty = tid >> 4;          // 4 kk x 4 c per thread
    unsigned long long acc[4][2];
#pragma unroll
    for (int i = 0; i < 4; i++) { acc[i][0] = 0ull; acc[i][1] = 0ull; }
#pragma unroll 4
    for (int j = 0; j < CC; j++) {
        float4 a = *(const float4*)&atts[j][ty*4];
        ulonglong2 xv = *(const ulonglong2*)&xfs[j][tx*4];
        unsigned long long d0 = dup2(a.x), d1 = dup2(a.y), d2 = dup2(a.z), d3 = dup2(a.w);
        fma2(acc[0][0], d0, xv.x); fma2(acc[0][1], d0, xv.y);
        fma2(acc[1][0], d1, xv.x); fma2(acc[1][1], d1, xv.y);
        fma2(acc[2][0], d2, xv.x); fma2(acc[2][1], d2, xv.y);
        fma2(acc[3][0], d3, xv.x); fma2(acc[3][1], d3, xv.y);
    }
    // scatter to transposed layout [n][(c*24+t)]
    int nn[4], tt2[4];
#pragma unroll
    for (int ki = 0; ki < 4; ki++) {
        int kk = k0 + tx*4 + ki;
        nn[ki] = kk / TT;
        tt2[ki] = kk - nn[ki]*TT;
    }
#pragma unroll
    for (int ci = 0; ci < 4; ci++) {
        int c = ty*4 + ci;
        float v[4] = { lo32(acc[ci][0]), hi32(acc[ci][0]),
                       lo32(acc[ci][1]), hi32(acc[ci][1]) };
#pragma unroll
        for (int ki = 0; ki < 4; ki++)
            g_x1t[((size_t)b*NN + nn[ki])*CT + c*TT + tt2[ki]] = v[ki];
    }
}

// ------------------------- K4: graph-attn projections (16 rows/block) ------
// weights (2 x 61KB) stay L1-resident across the 16 serial rows.
__global__ void __launch_bounds__(256) k_gatt_proj(const float* __restrict__ W2) {
    int base = blockIdx.x * 16;                // row = b*NN + n, 0..7999
    __shared__ float red[8][2*RR];
    int lane = threadIdx.x & 31, warp = threadIdx.x >> 5;
    for (int row = 0; row < 16; row++) {
        int bn = base + row;
        int b = bn / NN, n = bn - b*NN;
        const float* xf = g_x1t + (size_t)bn * CT;
        float a1[RR], a2[RR];
#pragma unroll
        for (int r = 0; r < RR; r++) { a1[r] = 0.f; a2[r] = 0.f; }
        for (int k4 = threadIdx.x * 4; k4 < CT; k4 += 1024) {
            float4 xv = *(const float4*)(xf + k4);
#pragma unroll
            for (int r = 0; r < RR; r++) {
                float4 w1 = *(const float4*)(g_gW1T + r*CT + k4);
                float4 w2 = *(const float4*)(W2 + r*CT + k4);
                a1[r] += xv.x*w1.x + xv.y*w1.y + xv.z*w1.z + xv.w*w1.w;
                a2[r] += xv.x*w2.x + xv.y*w2.y + xv.z*w2.z + xv.w*w2.w;
            }
        }
#pragma unroll
        for (int r = 0; r < RR; r++) {
#pragma unroll
            for (int off = 16; off > 0; off >>= 1) {
                a1[r] += __shfl_down_sync(0xffffffffu, a1[r], off);
                a2[r] += __shfl_down_sync(0xffffffffu, a2[r], off);
            }
        }
        if (lane == 0) {
#pragma unroll
            for (int r = 0; r < RR; r++) { red[warp][r] = a1[r]; red[warp][RR+r] = a2[r]; }
        }
        __syncthreads();
        if (threadIdx.x < 2*RR) {
            float s = 0.f;
#pragma unroll
            for (int w = 0; w < 8; w++) s += red[w][threadIdx.x];
            if (threadIdx.x < RR) g_s1g[(size_t)bn*RR + threadIdx.x] = s;
            else                  g_s2g[((size_t)b*RR + (threadIdx.x - RR))*NN + n] = s;
        }
        __syncthreads();
    }
}

// ------------------------- K5: graph softmax * A_adj -----------------------
__global__ void k_gatt_soft(const float* __restrict__ A_adj) {
    int bi = blockIdx.x;
    int b = bi / NN, i = bi - b*NN;
    __shared__ float sc[NN];
    __shared__ float s1r[RR];
    __shared__ float red[256];
    int tid = threadIdx.x;
    if (tid < RR) s1r[tid] = g_s1g[(size_t)(b*NN + i)*RR + tid];
    __syncthreads();
    float lmax = -1e30f;
    float scale = rsqrtf((float)CT);
    for (int j = tid; j < NN; j += 256) {
        float s = 0.f;
#pragma unroll
        for (int r = 0; r < RR; r++) s += s1r[r] * g_s2g[(size_t)(b*RR + r)*NN + j];
        s *= scale;
        sc[j] = s;
        lmax = fmaxf(lmax, s);
    }
    red[tid] = lmax; __syncthreads();
    for (int off = 128; off > 0; off >>= 1) {
        if (tid < off) red[tid] = fmaxf(red[tid], red[tid + off]);
        __syncthreads();
    }
    float mx = red[0];
    __syncthreads();
    float lsum = 0.f;
    for (int j = tid; j < NN; j += 256) {
        float e = expf(sc[j] - mx);
        sc[j] = e;
        lsum += e;
    }
    red[tid] = lsum; __syncthreads();
    for (int off = 128; off > 0; off >>= 1) {
        if (tid < off) red[tid] += red[tid + off];
        __syncthreads();
    }
    float inv = 1.f / red[0];
    for (int j = tid; j < NN; j += 256) {
        g_Ag[((size_t)b*NN + i)*NN + j] = sc[j] * inv * A_adj[i*NN + j];
    }
}

// ------------------------- K7: big GEMM g1 = Ag @ x1t (f32x2, pipelined) ---
#define GTM 128
#define GTN 128
#define GTK 16
__global__ void __launch_bounds__(256) k_gemm() {
    int b  = blockIdx.z;
    int n0 = blockIdx.y * GTM;
    int j0 = blockIdx.x * GTN;
    const float* A  = g_Ag  + (size_t)b*NN*NN;
    const float* Bm = g_x1t + (size_t)b*NN*CT;
    float*       Cm = g_g1  + (size_t)b*NN*CT;
    __shared__ float As[GTK][GTM + 4];
    __shared__ float Bs[GTK][GTN + 4];
    int tid = threadIdx.x;                     // 256
    int tx = tid & 15;
    int ty = tid >> 4;
    int an = tid >> 1, ah = (tid & 1) * 8;
    int bk = tid >> 4, bj = (tid & 15) * 8;
    const float4 z4 = make_float4(0.f, 0.f, 0.f, 0.f);

    unsigned long long acc[8][4];
#pragma unroll
    for (int i = 0; i < 8; i++)
#pragma unroll
        for (int j = 0; j < 4; j++) acc[i][j] = 0ull;

    float4 pa0, pa1, pb0, pb1;
    {
        int n = n0 + an;
        bool va = (n < NN) && (ah < NN);
        const float* pA = A + (size_t)n*NN + ah;
        pa0 = va ? *(const float4*)pA : z4;
        pa1 = va ? *(const float4*)(pA + 4) : z4;
        const float* pB = Bm + (size_t)bk*CT + j0 + bj;
        pb0 = *(const float4*)pB;
        pb1 = *(const float4*)(pB + 4);
    }
    const int NKT = (NN + GTK - 1) / GTK;      // 63
    for (int kt = 0; kt < NKT; kt++) {
        As[ah + 0][an] = pa0.x; As[ah + 1][an] = pa0.y;
        As[ah + 2][an] = pa0.z; As[ah + 3][an] = pa0.w;
        As[ah + 4][an] = pa1.x; As[ah + 5][an] = pa1.y;
        As[ah + 6][an] = pa1.z; As[ah + 7][an] = pa1.w;
        *(float4*)&Bs[bk][bj]     = pb0;
        *(float4*)&Bs[bk][bj + 4] = pb1;
        __syncthreads();
        if (kt + 1 < NKT) {
            int k0 = (kt + 1) * GTK;
            int n = n0 + an;
            bool va = (n < NN) && (k0 + ah < NN);
            const float* pA = A + (size_t)n*NN + k0 + ah;
            pa0 = va ? *(const float4*)pA : z4;
            pa1 = va ? *(const float4*)(pA + 4) : z4;
            bool vb = (k0 + bk < NN);
            const float* pB = Bm + (size_t)(k0 + bk)*CT + j0 + bj;
            pb0 = vb ? *(const float4*)pB : z4;
            pb1 = vb ? *(const float4*)(pB + 4) : z4;
        }
#pragma unroll
        for (int kk = 0; kk < GTK; kk++) {
            float4 a0 = *(const float4*)&As[kk][ty*8];
            float4 a1 = *(const float4*)&As[kk][ty*8 + 4];
            ulonglong2 b0 = *(const ulonglong2*)&Bs[kk][tx*8];
            ulonglong2 b1 = *(const ulonglong2*)&Bs[kk][tx*8 + 4];
            unsigned long long ad[8];
            ad[0] = dup2(a0.x); ad[1] = dup2(a0.y); ad[2] = dup2(a0.z); ad[3] = dup2(a0.w);
            ad[4] = dup2(a1.x); ad[5] = dup2(a1.y); ad[6] = dup2(a1.z); ad[7] = dup2(a1.w);
#pragma unroll
            for (int i = 0; i < 8; i++) {
                fma2(acc[i][0], ad[i], b0.x);
                fma2(acc[i][1], ad[i], b0.y);
                fma2(acc[i][2], ad[i], b1.x);
                fma2(acc[i][3], ad[i], b1.y);
            }
        }
        __syncthreads();
    }
#pragma unroll
    for (int i = 0; i < 8; i++) {
        int n = n0 + ty*8 + i;
        if (n < NN) {
            float* cp = Cm + (size_t)n*CT + j0 + tx*8;
            float4 v0 = make_float4(lo32(acc[i][0]), hi32(acc[i][0]),
                                    lo32(acc[i][1]), hi32(acc[i][1]));
            float4 v1 = make_float4(lo32(acc[i][2]), hi32(acc[i][2]),
                                    lo32(acc[i][3]), hi32(acc[i][3]));
            *(float4*)cp = v0;
            *(float4*)(cp + 4) = v1;
        }
    }
}

// ------------------------- K8: temporal-attn projections (fused W, 4t) -----
// s1t[b,t,r] = sum_{n,c} g1[b,n,c*T+t] * F1T[r][(n,c)]
__global__ void __launch_bounds__(256) k_tatt_proj() {
    int b  = blockIdx.x / 6;
    int tg = blockIdx.x - b*6;
    int t0 = tg * 4;
    const float* g1b = g_g1 + (size_t)b*NN*CT;
    unsigned long long a1p[2][RR], a2p[2][RR];
#pragma unroll
    for (int p = 0; p < 2; p++)
#pragma unroll
        for (int r = 0; r < RR; r++) { a1p[p][r] = 0ull; a2p[p][r] = 0ull; }

    for (int i4 = threadIdx.x * 4; i4 < NCO; i4 += 1024) {
        int n = i4 >> 6, c0 = i4 & 63;          // 4 consecutive c, same n
        const float* gp = g1b + (size_t)n*CT + c0*TT + t0;
        unsigned long long gq[4][2];
#pragma unroll
        for (int j = 0; j < 4; j++) {
            ulonglong2 gv = *(const ulonglong2*)(gp + j*TT);
            gq[j][0] = gv.x; gq[j][1] = gv.y;
        }
#pragma unroll
        for (int r = 0; r < RR; r++) {
            float4 f1 = *(const float4*)(g_F1T + (size_t)r*NCO + i4);
            float4 f2 = *(const float4*)(g_F2T + (size_t)r*NCO + i4);
            unsigned long long d;
            d = dup2(f1.x); fma2(a1p[0][r], d, gq[0][0]); fma2(a1p[1][r], d, gq[0][1]);
            d = dup2(f1.y); fma2(a1p[0][r], d, gq[1][0]); fma2(a1p[1][r], d, gq[1][1]);
            d = dup2(f1.z); fma2(a1p[0][r], d, gq[2][0]); fma2(a1p[1][r], d, gq[2][1]);
            d = dup2(f1.w); fma2(a1p[0][r], d, gq[3][0]); fma2(a1p[1][r], d, gq[3][1]);
            d = dup2(f2.x); fma2(a2p[0][r], d, gq[0][0]); fma2(a2p[1][r], d, gq[0][1]);
            d = dup2(f2.y); fma2(a2p[0][r], d, gq[1][0]); fma2(a2p[1][r], d, gq[1][1]);
            d = dup2(f2.z); fma2(a2p[0][r], d, gq[2][0]); fma2(a2p[1][r], d, gq[2][1]);
            d = dup2(f2.w); fma2(a2p[0][r], d, gq[3][0]); fma2(a2p[1][r], d, gq[3][1]);
        }
    }
    __shared__ unsigned long long redu[8][40];
    int lane = threadIdx.x & 31, warp = threadIdx.x >> 5;
#pragma unroll
    for (int p = 0; p < 2; p++)
#pragma unroll
        for (int r = 0; r < RR; r++) {
            unsigned long long v1 = a1p[p][r], v2 = a2p[p][r];
#pragma unroll
            for (int off = 16; off > 0; off >>= 1) {
                float l1 = lo32(v1) + __shfl_down_sync(0xffffffffu, lo32(v1), off);
                float h1 = hi32(v1) + __shfl_down_sync(0xffffffffu, hi32(v1), off);
                float l2 = lo32(v2) + __shfl_down_sync(0xffffffffu, lo32(v2), off);
                float h2 = hi32(v2) + __shfl_down_sync(0xffffffffu, hi32(v2), off);
                v1 = pack2(l1, h1); v2 = pack2(l2, h2);
            }
            if (lane == 0) {
                redu[warp][r*2 + p]      = v1;
                redu[warp][20 + r*2 + p] = v2;
            }
        }
    __syncthreads();
    int tid = threadIdx.x;
    if (tid < 40) {
        float slo = 0.f, shi = 0.f;
#pragma unroll
        for (int w = 0; w < 8; w++) {
            unsigned long long v = redu[w][tid];
            slo += lo32(v); shi += hi32(v);
        }
        int mat = tid / 20;
        int rem = tid - mat*20;
        int r = rem >> 1, p = rem & 1;
        int t = t0 + 2*p;
        if (mat == 0) {
            g_s1t[(b*TT + t)*RR + r]     = slo;
            g_s1t[(b*TT + t + 1)*RR + r] = shi;
        } else {
            g_s2t[(b*RR + r)*TT + t]     = slo;
            g_s2t[(b*RR + r)*TT + t + 1] = shi;
        }
    }
}

// ------------------------- K9: temporal softmax (24x24) --------------------
__global__ void k_tatt_soft() {
    int b = blockIdx.x;
    int i = threadIdx.x;
    if (i >= TT) return;
    float sc[TT];
    float scale = rsqrtf((float)NCO);
#pragma unroll
    for (int j = 0; j < TT; j++) {
        float s = 0.f;
#pragma unroll
        for (int r = 0; r < RR; r++) s += g_s1t[(b*TT + i)*RR + r] * g_s2t[(b*RR + r)*TT + j];
        sc[j] = s * scale;
    }
    float mx = -1e30f;
#pragma unroll
    for (int j = 0; j < TT; j++) mx = fmaxf(mx, sc[j]);
    float sum = 0.f;
#pragma unroll
    for (int j = 0; j < TT; j++) { sc[j] = expf(sc[j] - mx); sum += sc[j]; }
    float inv = 1.f / sum;
#pragma unroll
    for (int j = 0; j < TT; j++) g_attT[(b*TT + i)*TT + j] = sc[j] * inv;
}

// ------------------------- K10: fused mix + tatt-apply + convs + res + LN --
// 256 threads = 4 n-units x 64 o. Each thread owns (n, o), all 24 t in regs.
__global__ void __launch_bounds__(256) k_final(
        const float* __restrict__ x,
        const float* __restrict__ gcnW,
        const float* __restrict__ c1b,
        const float* __restrict__ c2b,
        const float* __restrict__ rb,
        const float* __restrict__ lng,
        const float* __restrict__ lnb,
        float* __restrict__ out) {
    __shared__ float smB[4*CT];                // 24 KB exchange buffer
    __shared__ float at_s[TT*TT];              // transposed: [tp][t]
    __shared__ float mu_s[4][TT], rs_s[4][TT];
    int blk = blockIdx.x;                      // 0..1999
    int b = blk / 250;
    int n0 = (blk - b*250) * 4;
    int tid = threadIdx.x;
    int u = tid >> 6, o = tid & 63;
    int n = n0 + u;

    // load g1 tiles (4 consecutive n rows = contiguous 4*CT range) + attT^T
    {
        const float* src = g_g1 + ((size_t)b*NN + n0)*CT;
        for (int e4 = tid; e4 < CT; e4 += 256)
            *(float4*)&smB[e4*4] = *(const float4*)(src + e4*4);
    }
    for (int e = tid; e < TT*TT; e += 256) {
        int t = e / TT, tp = e - t*TT;
        at_s[tp*TT + t] = g_attT[b*TT*TT + e];
    }
    __syncthreads();

    // ---- stage 0: gcn mix: gm[t] = sum_c gcnW[c,o] * g1[u][c*24+t] ----
    unsigned long long gmp[12];
#pragma unroll
    for (int k = 0; k < 12; k++) gmp[k] = 0ull;
#pragma unroll 4
    for (int c = 0; c < CC; c++) {
        unsigned long long wd = dup2(__ldg(gcnW + c*CC + o));
        const unsigned long long* pr = (const unsigned long long*)&smB[u*CT + c*TT];
#pragma unroll
        for (int k = 0; k < 12; k++) fma2(gmp[k], wd, pr[k]);
    }
    float gm[TT];
#pragma unroll
    for (int k = 0; k < 12; k++) { gm[2*k] = lo32(gmp[k]); gm[2*k+1] = hi32(gmp[k]); }

    // ---- stage A: temporal attention: x2p[t-pair] += at^T[tp] * gm[tp] ----
    unsigned long long x2p[12];
#pragma unroll
    for (int k = 0; k < 12; k++) x2p[k] = 0ull;
#pragma unroll 4
    for (int tp = 0; tp < TT; tp++) {
        unsigned long long gd = dup2(gm[tp]);
        const unsigned long long* ar = (const unsigned long long*)&at_s[tp*TT];
#pragma unroll
        for (int k = 0; k < 12; k++) fma2(x2p[k], gd, ar[k]);
    }
    __syncthreads();                            // stage-0 reads of smB done
    {
        unsigned long long* wp = (unsigned long long*)&smB[u*CT + o*TT];
#pragma unroll
        for (int k = 0; k < 12; k++) wp[k] = x2p[k];
    }
    __syncthreads();

    // ---- conv1 (d=1), packed f32x2 over t-pairs ----
    unsigned long long yp[12];
    {
        unsigned long long bias = dup2(__ldg(c1b + o));
#pragma unroll
        for (int k = 0; k < 12; k++) yp[k] = bias;
#pragma unroll 4
        for (int c = 0; c < CC; c++) {
            const unsigned long long* pr = (const unsigned long long*)&smB[u*CT + c*TT];
            unsigned long long w0d = dup2(__ldg(g_w1T + c*CC + o));
            unsigned long long w1d = dup2(__ldg(g_w1T + CC*CC + c*CC + o));
            unsigned long long tp_[12];
#pragma unroll
            for (int k = 0; k < 12; k++) tp_[k] = pr[k];
#pragma unroll
            for (int k = 0; k < 12; k++) fma2(yp[k], w1d, tp_[k]);
            unsigned long long sh = pack2(0.f, lo32(tp_[0]));
            fma2(yp[0], w0d, sh);
#pragma unroll
            for (int k = 1; k < 12; k++) {
                sh = pack2(hi32(tp_[k-1]), lo32(tp_[k]));
                fma2(yp[k], w0d, sh);
            }
        }
    }
    float y1[TT];
#pragma unroll
    for (int k = 0; k < 12; k++) {
        y1[2*k]   = fmaxf(lo32(yp[k]), 0.f);
        y1[2*k+1] = fmaxf(hi32(yp[k]), 0.f);
    }
    __syncthreads();                            // conv1 reads of smB done
    {
        float* wp = &smB[u*CT + o*TT];
#pragma unroll
        for (int k = 0; k < 6; k++)
            *(float4*)(wp + 4*k) = make_float4(y1[4*k], y1[4*k+1], y1[4*k+2], y1[4*k+3]);
    }
    __syncthreads();

    // ---- conv2 (d=2): pair-aligned shift ----
    unsigned long long vp[12];
    {
        unsigned long long bias = dup2(__ldg(c2b + o));
#pragma unroll
        for (int k = 0; k < 12; k++) vp[k] = bias;
#pragma unroll 4
        for (int c = 0; c < CC; c++) {
            const unsigned long long* pr = (const unsigned long long*)&smB[u*CT + c*TT];
            unsigned long long w0d = dup2(__ldg(g_w2T + c*CC + o));
            unsigned long long w1d = dup2(__ldg(g_w2T + CC*CC + c*CC + o));
            unsigned long long prev = 0ull;
#pragma unroll
            for (int k = 0; k < 12; k++) {
                unsigned long long cur = pr[k];
                fma2(vp[k], w1d, cur);
                fma2(vp[k], w0d, prev);
                prev = cur;
            }
        }
    }
#pragma unroll
    for (int k = 0; k < 12; k++)
        vp[k] = pack2(fmaxf(lo32(vp[k]), 0.f), fmaxf(hi32(vp[k]), 0.f));
    __syncthreads();                            // conv2 reads done

    // load original x into smB
    for (int e4 = tid; e4 < CT; e4 += 256) {
        int f = e4 * 4;
        int u2 = f / CT, rem = f - u2*CT;
        int c = rem / TT, t = rem - c*TT;
        *(float4*)&smB[f] = *(const float4*)(x + (size_t)((b*CC + c)*NN + n0 + u2)*TT + t);
    }
    __syncthreads();

    // ---- residual 1x1 + relu ----
#pragma unroll 4
    for (int c = 0; c < CC; c++) {
        const unsigned long long* pr = (const unsigned long long*)&smB[u*CT + c*TT];
        unsigned long long rwd = dup2(__ldg(g_rT + c*CC + o));
#pragma unroll
        for (int k = 0; k < 12; k++) fma2(vp[k], rwd, pr[k]);
    }
    {
        float biasr = __ldg(rb + o);
#pragma unroll
        for (int k = 0; k < 12; k++) {
            float lo = fmaxf(lo32(vp[k]) + biasr, 0.f);
            float hi = fmaxf(hi32(vp[k]) + biasr, 0.f);
            vp[k] = pack2(lo, hi);
        }
    }
    float v[TT];
#pragma unroll
    for (int k = 0; k < 12; k++) { v[2*k] = lo32(vp[k]); v[2*k+1] = hi32(vp[k]); }
    __syncthreads();                            // residual reads done

    // ---- LayerNorm over o (64) per (u,t) ----
    {
        float* wp = &smB[u*CT + o*TT];
#pragma unroll
        for (int k = 0; k < 6; k++)
            *(float4*)(wp + 4*k) = make_float4(v[4*k], v[4*k+1], v[4*k+2], v[4*k+3]);
    }
    __syncthreads();
    if (tid < 96) {
        int ur = tid / TT, tr = tid - ur*TT;
        float S = 0.f, Q = 0.f;
#pragma unroll 8
        for (int oo = 0; oo < CC; oo++) {
            float val = smB[ur*CT + oo*TT + tr];
            S += val; Q += val*val;
        }
        float mu = S * (1.f/CC);
        float var = Q * (1.f/CC) - mu*mu;
        mu_s[ur][tr] = mu;
        rs_s[ur][tr] = rsqrtf(var + 1e-5f);
    }
    __syncthreads();
    {
        float gmul = __ldg(lng + o), badd = __ldg(lnb + o);
        float* op = out + (size_t)((b*CC + o)*NN + n)*TT;
        float res[TT];
#pragma unroll
        for (int t = 0; t < TT; t++)
            res[t] = (v[t] - mu_s[u][t]) * rs_s[u][t] * gmul + badd;
#pragma unroll
        for (int k = 0; k < 6; k++)
            *(float4*)(op + 4*k) = make_float4(res[4*k], res[4*k+1], res[4*k+2], res[4*k+3]);
    }
}

// ------------------------- launch ------------------------------------------
extern "C" void kernel_launch(void* const* d_in, const int* in_sizes, int n_in,
                              void* d_out, int out_size) {
    const float* x     = (const float*)d_in[0];
    const float* A_adj = (const float*)d_in[1];
    const float* a0W1  = (const float*)d_in[2];
    const float* a0W2  = (const float*)d_in[3];
    const float* gW1   = (const float*)d_in[4];
    const float* gW2   = (const float*)d_in[5];
    const float* gcnW  = (const float*)d_in[6];
    const float* tW1   = (const float*)d_in[7];
    const float* tW2   = (const float*)d_in[8];
    const float* c1w   = (const float*)d_in[9];
    const float* c1b   = (const float*)d_in[10];
    const float* c2w   = (const float*)d_in[11];
    const float* c2b   = (const float*)d_in[12];
    const float* resw  = (const float*)d_in[13];
    const float* resb  = (const float*)d_in[14];
    const float* lng   = (const float*)d_in[15];
    const float* lnb   = (const float*)d_in[16];
    float* out = (float*)d_out;

    k_prep<<<1014, 256>>>(a0W1, gW1, c1w, c2w, resw);
    k_fuse<<<NN, 256>>>(gcnW, tW1, tW2);
    k_attA_proj<<<BB*CC/4, 256>>>(x, a0W2);
    k_attA_soft<<<BB*CC, CC>>>();
    k_chan_apply<<<dim3(NT/64, BB), 256>>>(x);
    k_gatt_proj<<<BB*NN/16, 256>>>(gW2);
    k_gatt_soft<<<BB*NN, 256>>>(A_adj);
    k_gemm<<<dim3(CT/GTN, (NN + GTM - 1)/GTM, BB), 256>>>();
    k_tatt_proj<<<BB*6, 256>>>();
    k_tatt_soft<<<BB, 32>>>();
    k_final<<<BB*NN/4, 256>>>(x, gcnW, c1b, c2b, resb, lng, lnb, out);
}